// round 4
// baseline (speedup 1.0000x reference)
#include <cuda_runtime.h>
#include <cuda_bf16.h>
#include <cstdint>

static constexpr int B_  = 8;
static constexpr int N_  = 16384;
static constexpr int S_  = 2048;
static constexpr int C1_ = 128;
static constexpr int C2_ = 256;
static constexpr int K1_ = 384;
static constexpr int O_  = 256;
static constexpr float BN_EPS  = 1e-5f;
static constexpr float CNT_INV = 1.0f / (float)(B_ * N_);
static constexpr float QS   = 8.0f / 127.0f;   // static activation scale
static constexpr float QINV = 127.0f / 8.0f;

// ---------------- device-global scratch (no cudaMalloc allowed) ---------------
__device__ int8_t g_xqh[(size_t)B_ * N_ * K1_];  // concat input q-hi [n][k]
__device__ int8_t g_xql[(size_t)B_ * N_ * K1_];  // concat input q-lo
__device__ float  g_y [(size_t)B_ * N_ * O_];    // y1 then y2 (n-major)
__device__ int8_t g_hqh[(size_t)B_ * N_ * O_];   // layer2 input q-hi
__device__ int8_t g_hql[(size_t)B_ * N_ * O_];   // layer2 input q-lo
__device__ float  g_p2t[(size_t)B_ * S_ * C2_];  // points2 transposed [B][S][C]
__device__ int    g_idx[(size_t)B_ * N_ * 3];
__device__ float  g_w  [(size_t)B_ * N_ * 3];
__device__ int8_t g_aq0h[O_ * K1_], g_aq0l[O_ * K1_];
__device__ int8_t g_aq1h[O_ * O_],  g_aq1l[O_ * O_];
__device__ float  g_wsa0[O_], g_wsa1[O_];
__device__ float  g_psum[256 * 2048], g_pssq[256 * 2048];
__device__ float  g_sb1[512], g_sb2[512];

// ---------------- small PTX helpers ------------------------------------------
__device__ __forceinline__ uint32_t smem_u32(const void* p) {
    uint32_t a;
    asm("{ .reg .u64 t; cvta.to.shared.u64 t, %1; cvt.u32.u64 %0, t; }"
        : "=r"(a) : "l"(p));
    return a;
}
__device__ __forceinline__ void cpa16(uint32_t dst, const void* src) {
    asm volatile("cp.async.cg.shared.global [%0], [%1], 16;"
                 :: "r"(dst), "l"(src) : "memory");
}
#define CP_COMMIT() asm volatile("cp.async.commit_group;" ::: "memory")
#define CP_WAIT0()  asm volatile("cp.async.wait_group 0;" ::: "memory")
#define CP_WAIT1()  asm volatile("cp.async.wait_group 1;" ::: "memory")

__device__ __forceinline__ void ldsm4(uint32_t addr, uint32_t* r) {
    asm volatile("ldmatrix.sync.aligned.m8n8.x4.shared.b16 {%0,%1,%2,%3}, [%4];"
                 : "=r"(r[0]), "=r"(r[1]), "=r"(r[2]), "=r"(r[3]) : "r"(addr));
}
__device__ __forceinline__ void mma_i8(int* c, const uint32_t* a, const uint32_t* b) {
    asm volatile(
        "mma.sync.aligned.m16n8k32.row.col.s32.s8.s8.s32 "
        "{%0,%1,%2,%3}, {%4,%5,%6,%7}, {%8,%9}, {%0,%1,%2,%3};"
        : "+r"(c[0]), "+r"(c[1]), "+r"(c[2]), "+r"(c[3])
        : "r"(a[0]), "r"(a[1]), "r"(a[2]), "r"(a[3]), "r"(b[0]), "r"(b[1]));
}

__device__ __forceinline__ int clamp127(int v) {
    return v < -127 ? -127 : (v > 127 ? 127 : v);
}
// 2-level quantization with scale s (lo scale = s/128)
__device__ __forceinline__ void quant2(float v, float s, float inv,
                                       int8_t& qh, int8_t& ql) {
    int h = clamp127(__float2int_rn(v * inv));
    float r = fmaf((float)(-h), s, v);
    int l = clamp127(__float2int_rn(r * inv * 128.0f));
    qh = (int8_t)h; ql = (int8_t)l;
}

// ---------------- kNN (4 queries per thread) ---------------------------------
__global__ __launch_bounds__(256) void knn_kernel(
    const float* __restrict__ xyz1, const float* __restrict__ xyz2)
{
    __shared__ float4 sp[S_];
    const int b = blockIdx.y;
    const int t = threadIdx.x;
    for (int s = t; s < S_; s += 256) {
        const float* p = xyz2 + ((size_t)b * S_ + s) * 3;
        sp[s] = make_float4(p[0], p[1], p[2], 0.0f);
    }
    __syncthreads();

    const int nb = blockIdx.x * 1024 + t;
    float qx[4], qy[4], qz[4];
    float d0[4], d1[4], d2[4];
    int   i0[4], i1[4], i2[4];
    #pragma unroll
    for (int j = 0; j < 4; j++) {
        const float* q = xyz1 + ((size_t)b * N_ + nb + j * 256) * 3;
        qx[j] = q[0]; qy[j] = q[1]; qz[j] = q[2];
        d0[j] = 3.4e38f; d1[j] = 3.4e38f; d2[j] = 3.4e38f;
        i0[j] = 0; i1[j] = 0; i2[j] = 0;
    }
    #pragma unroll 2
    for (int s = 0; s < S_; s++) {
        float4 p = sp[s];
        #pragma unroll
        for (int j = 0; j < 4; j++) {
            float dx = qx[j] - p.x, dy = qy[j] - p.y, dz = qz[j] - p.z;
            float d = fmaf(dz, dz, fmaf(dy, dy, dx * dx));
            if (d < d2[j]) {
                if (d < d1[j]) {
                    d2[j] = d1[j]; i2[j] = i1[j];
                    if (d < d0[j]) { d1[j] = d0[j]; i1[j] = i0[j]; d0[j] = d; i0[j] = s; }
                    else           { d1[j] = d;  i1[j] = s; }
                } else { d2[j] = d; i2[j] = s; }
            }
        }
    }
    #pragma unroll
    for (int j = 0; j < 4; j++) {
        float a = fmaxf(d0[j], 1e-10f), bb = fmaxf(d1[j], 1e-10f), c = fmaxf(d2[j], 1e-10f);
        float w0 = 1.0f / a, w1 = 1.0f / bb, w2 = 1.0f / c;
        float sw = w0 + w1 + w2;
        size_t base = ((size_t)b * N_ + nb + j * 256) * 3;
        g_idx[base] = i0[j]; g_idx[base + 1] = i1[j]; g_idx[base + 2] = i2[j];
        g_w[base] = w0 / sw; g_w[base + 1] = w1 / sw; g_w[base + 2] = w2 / sw;
    }
}

// ---------------- transpose points2 [B][C][S] -> [B][S][C] --------------------
__global__ void transpose_p2_kernel(const float* __restrict__ p2)
{
    __shared__ float tile[32][33];
    const int b  = blockIdx.z;
    const int s0 = blockIdx.x * 32;
    const int c0 = blockIdx.y * 32;
    #pragma unroll
    for (int r = 0; r < 4; r++) {
        int c = c0 + threadIdx.y + r * 8;
        tile[threadIdx.y + r * 8][threadIdx.x] =
            p2[((size_t)b * C2_ + c) * S_ + s0 + threadIdx.x];
    }
    __syncthreads();
    #pragma unroll
    for (int r = 0; r < 4; r++) {
        int s = s0 + threadIdx.y + r * 8;
        g_p2t[((size_t)b * S_ + s) * C2_ + c0 + threadIdx.x] =
            tile[threadIdx.x][threadIdx.y + r * 8];
    }
}

// ---------------- gather + weighted sum + quantize -> channels [0,256) --------
__global__ __launch_bounds__(256) void gather_kernel()
{
    const int b  = blockIdx.y;
    const int n0 = blockIdx.x * 32;
    const int t  = threadIdx.x;          // channel
    #pragma unroll 2
    for (int nl = 0; nl < 32; nl++) {
        size_t base = ((size_t)b * N_ + n0 + nl) * 3;
        int i0 = g_idx[base], i1 = g_idx[base + 1], i2 = g_idx[base + 2];
        float w0 = g_w[base], w1 = g_w[base + 1], w2 = g_w[base + 2];
        const float* r0 = g_p2t + ((size_t)b * S_ + i0) * C2_;
        const float* r1 = g_p2t + ((size_t)b * S_ + i1) * C2_;
        const float* r2 = g_p2t + ((size_t)b * S_ + i2) * C2_;
        float v = fmaf(w2, r2[t], fmaf(w1, r1[t], w0 * r0[t]));
        int8_t qh, ql; quant2(v, QS, QINV, qh, ql);
        size_t o = ((size_t)b * N_ + n0 + nl) * K1_ + t;
        g_xqh[o] = qh; g_xql[o] = ql;
    }
}

// ---------------- points1 transpose + quantize -> channels [256,384) ----------
__global__ void p1t_kernel(const float* __restrict__ p1)
{
    __shared__ float tile[32][33];
    const int b  = blockIdx.z;
    const int n0 = blockIdx.x * 32;
    const int c0 = blockIdx.y * 32;
    #pragma unroll
    for (int r = 0; r < 4; r++) {
        int c = c0 + threadIdx.y + r * 8;
        tile[threadIdx.y + r * 8][threadIdx.x] =
            p1[((size_t)b * C1_ + c) * N_ + n0 + threadIdx.x];
    }
    __syncthreads();
    #pragma unroll
    for (int r = 0; r < 4; r++) {
        int n = n0 + threadIdx.y + r * 8;
        float v = tile[threadIdx.x][threadIdx.y + r * 8];
        int8_t qh, ql; quant2(v, QS, QINV, qh, ql);
        size_t o = ((size_t)b * N_ + n) * K1_ + 256 + c0 + threadIdx.x;
        g_xqh[o] = qh; g_xql[o] = ql;
    }
}

// ---------------- weight quantization: per-row scale, 2 levels ----------------
__global__ __launch_bounds__(256) void wquant_kernel(
    const float* __restrict__ w, int kdim,
    int8_t* __restrict__ qh, int8_t* __restrict__ ql,
    float* __restrict__ wsa)
{
    const int lane = threadIdx.x & 31;
    const int row  = blockIdx.x * 8 + (threadIdx.x >> 5);
    const float* wr = w + (size_t)row * kdim;
    float m = 0.0f;
    for (int k = lane; k < kdim; k += 32) m = fmaxf(m, fabsf(wr[k]));
    #pragma unroll
    for (int off = 16; off; off >>= 1)
        m = fmaxf(m, __shfl_xor_sync(0xffffffffu, m, off));
    float sA = (m > 0.0f) ? m / 127.0f : 1.0f;
    float inv = 127.0f / ((m > 0.0f) ? m : 1.0f);
    for (int k = lane; k < kdim; k += 32) {
        int8_t h, l; quant2(wr[k], sA, inv, h, l);
        qh[(size_t)row * kdim + k] = h;
        ql[(size_t)row * kdim + k] = l;
    }
    if (lane == 0) wsa[row] = sA;
}

// ---------------- int8 mma.sync GEMM (2-level decomposition) ------------------
// CTA: 256 thr = 8 warps (4 in M x 2 in N). CTA tile M=256 x N=64, warp 64x32.
// D = sA[m]*QS*(accHH + accX/128) + bias.  Y n-major via smem-staged flush.
template<int KDIM>
__global__ __launch_bounds__(256) void gemm_i8(
    const int8_t* __restrict__ Ah, const int8_t* __restrict__ Al,
    const int8_t* __restrict__ Bh, const int8_t* __restrict__ Bl,
    const float* __restrict__ wsa, const float* __restrict__ bias,
    float* __restrict__ Y, float* __restrict__ psum, float* __restrict__ pssq)
{
    constexpr int NS = KDIM / 64;                 // K stages of 64 bytes
    constexpr uint32_t PITCH  = 80;               // 64B data + 16B pad
    constexpr uint32_t OFF_AL = 256u * PITCH;     // 20480
    constexpr uint32_t OFF_B  = 2u * OFF_AL;      // 40960
    constexpr uint32_t OFF_BL = 64u * PITCH;      // 5120
    constexpr uint32_t STAGE  = OFF_B + 2u * OFF_BL;  // 51200

    extern __shared__ char sdyn[];
    __shared__ float sm_s[2][256], sm_q[2][256];

    const int tid  = threadIdx.x;
    const int lane = tid & 31, wid = tid >> 5;
    const int mw   = wid & 3;        // M block of 64
    const int nw   = wid >> 2;       // N block of 32
    const int b    = blockIdx.y;
    const int n0   = blockIdx.x * 64;
    const size_t bn0 = (size_t)b * N_ + n0;
    const uint32_t sb0 = smem_u32(sdyn);

    auto load_stage = [&](int kt, int buf) {
        uint32_t base = sb0 + (uint32_t)buf * STAGE;
        #pragma unroll
        for (int i = 0; i < 8; i++) {              // A: 2 var x 256 rows x 4 chunks
            int c = tid + i * 256;
            int var = c >> 10, row = (c >> 2) & 255, ch = c & 3;
            const int8_t* src = (var ? Al : Ah) + (size_t)row * KDIM + kt + ch * 16;
            cpa16(base + (uint32_t)var * OFF_AL + (uint32_t)row * PITCH + ch * 16, src);
        }
        #pragma unroll
        for (int i = 0; i < 2; i++) {              // B: 2 var x 64 rows x 4 chunks
            int c = tid + i * 256;
            int var = c >> 8, row = (c >> 2) & 63, ch = c & 3;
            const int8_t* src = (var ? Bl : Bh) + (bn0 + row) * KDIM + kt + ch * 16;
            cpa16(base + OFF_B + (uint32_t)var * OFF_BL + (uint32_t)row * PITCH + ch * 16, src);
        }
        CP_COMMIT();
    };

    int accH[4][4][4] = {};
    int accX[4][4][4] = {};

    load_stage(0, 0);

    #pragma unroll 1
    for (int s = 0; s < NS; s++) {
        if (s + 1 < NS) { load_stage((s + 1) * 64, (s + 1) & 1); CP_WAIT1(); }
        else            { CP_WAIT0(); }
        __syncthreads();

        uint32_t base = sb0 + (uint32_t)(s & 1) * STAGE;
        #pragma unroll
        for (int ks = 0; ks < 2; ks++) {
            uint32_t a[2][4][4];
            #pragma unroll
            for (int var = 0; var < 2; var++)
                #pragma unroll
                for (int mt = 0; mt < 4; mt++) {
                    uint32_t row = (uint32_t)(mw * 64 + mt * 16 + (lane & 15));
                    ldsm4(base + (uint32_t)var * OFF_AL + row * PITCH
                          + ks * 32 + ((lane >> 4) << 4), a[var][mt]);
                }
            uint32_t bb[2][2][4];
            #pragma unroll
            for (int var = 0; var < 2; var++)
                #pragma unroll
                for (int pair = 0; pair < 2; pair++) {
                    uint32_t row = (uint32_t)(nw * 32 + pair * 16
                                   + ((lane >> 4) & 1) * 8 + (lane & 7));
                    ldsm4(base + OFF_B + (uint32_t)var * OFF_BL + row * PITCH
                          + ks * 32 + (((lane >> 3) & 1) << 4), bb[var][pair]);
                }
            #pragma unroll
            for (int nt = 0; nt < 4; nt++) {
                const uint32_t* bh = &bb[0][nt >> 1][(nt & 1) * 2];
                const uint32_t* bl = &bb[1][nt >> 1][(nt & 1) * 2];
                #pragma unroll
                for (int mt = 0; mt < 4; mt++) {
                    mma_i8(accH[mt][nt], a[0][mt], bh);
                    mma_i8(accX[mt][nt], a[0][mt], bl);
                    mma_i8(accX[mt][nt], a[1][mt], bh);
                }
            }
        }
        __syncthreads();
    }

    // ---- epilogue: combine scales, BN partials, smem-staged coalesced flush --
    __syncthreads();                      // all warps done reading stage buffers
    float* sy = (float*)sdyn;             // [64][260]
    const int r = lane >> 2;
    float csum[8] = {}, cssq[8] = {};
    #pragma unroll
    for (int mt = 0; mt < 4; mt++) {
        const int m0 = mw * 64 + mt * 16 + r;
        const int m1 = m0 + 8;
        const float f0 = wsa[m0] * QS, fx0 = f0 * (1.0f / 128.0f);
        const float f1 = wsa[m1] * QS, fx1 = f1 * (1.0f / 128.0f);
        const float bv0 = bias[m0], bv1 = bias[m1];
        #pragma unroll
        for (int nt = 0; nt < 4; nt++) {
            int* cH = accH[mt][nt];
            int* cX = accX[mt][nt];
            int nl = nw * 32 + nt * 8 + (lane & 3) * 2;
            float v0 = fmaf(f0, (float)cH[0], fmaf(fx0, (float)cX[0], bv0));
            float v1 = fmaf(f0, (float)cH[1], fmaf(fx0, (float)cX[1], bv0));
            float v2 = fmaf(f1, (float)cH[2], fmaf(fx1, (float)cX[2], bv1));
            float v3 = fmaf(f1, (float)cH[3], fmaf(fx1, (float)cX[3], bv1));
            sy[nl * 260 + m0]       = v0;
            sy[(nl + 1) * 260 + m0] = v1;
            sy[nl * 260 + m1]       = v2;
            sy[(nl + 1) * 260 + m1] = v3;
            csum[mt * 2]     += v0 + v1;
            cssq[mt * 2]     += fmaf(v0, v0, v1 * v1);
            csum[mt * 2 + 1] += v2 + v3;
            cssq[mt * 2 + 1] += fmaf(v2, v2, v3 * v3);
        }
    }
    #pragma unroll
    for (int j = 0; j < 8; j++) {
        csum[j] += __shfl_xor_sync(0xffffffffu, csum[j], 1);
        csum[j] += __shfl_xor_sync(0xffffffffu, csum[j], 2);
        cssq[j] += __shfl_xor_sync(0xffffffffu, cssq[j], 1);
        cssq[j] += __shfl_xor_sync(0xffffffffu, cssq[j], 2);
    }
    if ((lane & 3) == 0) {
        #pragma unroll
        for (int mt = 0; mt < 4; mt++) {
            #pragma unroll
            for (int h = 0; h < 2; h++) {
                int ch = mw * 64 + mt * 16 + r + h * 8;
                sm_s[nw][ch] = csum[mt * 2 + h];
                sm_q[nw][ch] = cssq[mt * 2 + h];
            }
        }
    }
    __syncthreads();
    {
        int cta = blockIdx.x + blockIdx.y * gridDim.x;
        psum[tid * 2048 + cta] = sm_s[0][tid] + sm_s[1][tid];
        pssq[tid * 2048 + cta] = sm_q[0][tid] + sm_q[1][tid];
        // coalesced flush: one 1KB row per iteration
        #pragma unroll 4
        for (int n = 0; n < 64; n++)
            Y[(bn0 + n) * 256 + tid] = sy[n * 260 + tid];
    }
}

// ---------------- BN fold: reduce 2048 partials per channel -------------------
__global__ __launch_bounds__(256) void stats2_kernel(
    const float* __restrict__ g, const float* __restrict__ beta,
    float* __restrict__ sb)
{
    const int o = blockIdx.x;
    const int t = threadIdx.x;
    float s = 0.0f, ss = 0.0f;
    #pragma unroll
    for (int i = 0; i < 8; i++) {
        s  += g_psum[o * 2048 + t * 8 + i];
        ss += g_pssq[o * 2048 + t * 8 + i];
    }
    const int lane = t & 31, w = t >> 5;
    #pragma unroll
    for (int off = 16; off; off >>= 1) {
        s  += __shfl_down_sync(0xffffffffu, s,  off);
        ss += __shfl_down_sync(0xffffffffu, ss, off);
    }
    __shared__ float rs[8], rss[8];
    if (lane == 0) { rs[w] = s; rss[w] = ss; }
    __syncthreads();
    if (t == 0) {
        float ts = 0.0f, tss = 0.0f;
        #pragma unroll
        for (int i = 0; i < 8; i++) { ts += rs[i]; tss += rss[i]; }
        float mean = ts * CNT_INV;
        float var  = tss * CNT_INV - mean * mean;
        float rstd = rsqrtf(var + BN_EPS);
        float sc = g[o] * rstd;
        sb[o]       = sc;
        sb[256 + o] = beta[o] - mean * sc;
    }
}

// ---------------- layer-1 norm + relu + quantize -> h -------------------------
__global__ __launch_bounds__(256) void splitq_kernel(
    const float* __restrict__ y, const float* __restrict__ sb)
{
    size_t i4 = (size_t)blockIdx.x * 256 + threadIdx.x;   // over B*N*64
    int c4 = (int)(i4 & 63) * 4;
    float4 v  = ((const float4*)y)[i4];
    float4 sc = *(const float4*)(sb + c4);
    float4 bs = *(const float4*)(sb + 256 + c4);
    float a0 = fmaxf(fmaf(v.x, sc.x, bs.x), 0.0f);
    float a1 = fmaxf(fmaf(v.y, sc.y, bs.y), 0.0f);
    float a2 = fmaxf(fmaf(v.z, sc.z, bs.z), 0.0f);
    float a3 = fmaxf(fmaf(v.w, sc.w, bs.w), 0.0f);
    char4 h, l;
    int8_t qh, ql;
    quant2(a0, QS, QINV, qh, ql); h.x = qh; l.x = ql;
    quant2(a1, QS, QINV, qh, ql); h.y = qh; l.y = ql;
    quant2(a2, QS, QINV, qh, ql); h.z = qh; l.z = ql;
    quant2(a3, QS, QINV, qh, ql); h.w = qh; l.w = ql;
    ((char4*)g_hqh)[i4] = h;
    ((char4*)g_hql)[i4] = l;
}

// ---------------- final norm + relu + transpose -> out [B][256][N] ------------
__global__ __launch_bounds__(256) void outt_kernel(
    const float* __restrict__ y, const float* __restrict__ sb,
    float* __restrict__ out)
{
    __shared__ float tile[32][33];
    const int b  = blockIdx.z;
    const int n0 = blockIdx.x * 32;
    const int m0 = blockIdx.y * 32;
    const float sc = sb[m0 + threadIdx.x];
    const float bs = sb[256 + m0 + threadIdx.x];
    #pragma unroll
    for (int r = 0; r < 4; r++) {
        int n = n0 + threadIdx.y + r * 8;
        float v = y[((size_t)b * N_ + n) * 256 + m0 + threadIdx.x];
        tile[threadIdx.y + r * 8][threadIdx.x] = fmaxf(fmaf(v, sc, bs), 0.0f);
    }
    __syncthreads();
    #pragma unroll
    for (int r = 0; r < 4; r++) {
        int m = m0 + threadIdx.y + r * 8;
        out[((size_t)b * 256 + m) * N_ + n0 + threadIdx.x] =
            tile[threadIdx.x][threadIdx.y + r * 8];
    }
}

// ---------------- launcher ----------------------------------------------------
extern "C" void kernel_launch(void* const* d_in, const int* in_sizes, int n_in,
                              void* d_out, int out_size)
{
    const float* xyz1 = (const float*)d_in[0];
    const float* xyz2 = (const float*)d_in[1];
    const float* pts1 = (const float*)d_in[2];
    const float* pts2 = (const float*)d_in[3];
    const float* W0   = (const float*)d_in[4];
    const float* b0   = (const float*)d_in[5];
    const float* gg0  = (const float*)d_in[6];
    const float* be0  = (const float*)d_in[7];
    const float* W1   = (const float*)d_in[8];
    const float* b1   = (const float*)d_in[9];
    const float* gg1  = (const float*)d_in[10];
    const float* be1  = (const float*)d_in[11];
    float* out = (float*)d_out;

    int8_t *xqh, *xql, *hqh, *hql, *aq0h, *aq0l, *aq1h, *aq1l;
    float *y, *psum, *pssq, *sb1, *sb2, *wsa0, *wsa1;
    cudaGetSymbolAddress((void**)&xqh,  g_xqh);
    cudaGetSymbolAddress((void**)&xql,  g_xql);
    cudaGetSymbolAddress((void**)&hqh,  g_hqh);
    cudaGetSymbolAddress((void**)&hql,  g_hql);
    cudaGetSymbolAddress((void**)&aq0h, g_aq0h);
    cudaGetSymbolAddress((void**)&aq0l, g_aq0l);
    cudaGetSymbolAddress((void**)&aq1h, g_aq1h);
    cudaGetSymbolAddress((void**)&aq1l, g_aq1l);
    cudaGetSymbolAddress((void**)&wsa0, g_wsa0);
    cudaGetSymbolAddress((void**)&wsa1, g_wsa1);
    cudaGetSymbolAddress((void**)&y,    g_y);
    cudaGetSymbolAddress((void**)&psum, g_psum);
    cudaGetSymbolAddress((void**)&pssq, g_pssq);
    cudaGetSymbolAddress((void**)&sb1,  g_sb1);
    cudaGetSymbolAddress((void**)&sb2,  g_sb2);

    const int GEMM_SMEM = 2 * 51200;   // 100 KB double-buffered stages
    cudaFuncSetAttribute(gemm_i8<K1_>, cudaFuncAttributeMaxDynamicSharedMemorySize, GEMM_SMEM);
    cudaFuncSetAttribute(gemm_i8<O_>,  cudaFuncAttributeMaxDynamicSharedMemorySize, GEMM_SMEM);

    // prep
    wquant_kernel<<<32, 256>>>(W0, K1_, aq0h, aq0l, wsa0);
    wquant_kernel<<<32, 256>>>(W1, O_,  aq1h, aq1l, wsa1);
    knn_kernel<<<dim3(N_ / 1024, B_), 256>>>(xyz1, xyz2);
    transpose_p2_kernel<<<dim3(S_ / 32, C2_ / 32, B_), dim3(32, 8)>>>(pts2);
    gather_kernel<<<dim3(N_ / 32, B_), 256>>>();
    p1t_kernel<<<dim3(N_ / 32, C1_ / 32, B_), dim3(32, 8)>>>(pts1);

    // layer 1
    gemm_i8<K1_><<<dim3(N_ / 64, B_), 256, GEMM_SMEM>>>(aq0h, aq0l, xqh, xql,
                                                        wsa0, b0, y, psum, pssq);
    stats2_kernel<<<256, 256>>>(gg0, be0, sb1);
    splitq_kernel<<<(int)((size_t)B_ * N_ * 64 / 256), 256>>>(y, sb1);

    // layer 2
    gemm_i8<O_><<<dim3(N_ / 64, B_), 256, GEMM_SMEM>>>(aq1h, aq1l, hqh, hql,
                                                       wsa1, b1, y, psum, pssq);
    stats2_kernel<<<256, 256>>>(gg1, be1, sb2);

    // output
    outt_kernel<<<dim3(N_ / 32, 8, B_), dim3(32, 8)>>>(y, sb2, out);
}

// round 5
// speedup vs baseline: 1.6628x; 1.6628x over previous
#include <cuda_runtime.h>
#include <cuda_bf16.h>
#include <cstdint>

static constexpr int B_  = 8;
static constexpr int N_  = 16384;
static constexpr int S_  = 2048;
static constexpr int C1_ = 128;
static constexpr int C2_ = 256;
static constexpr int K1_ = 384;
static constexpr int O_  = 256;
static constexpr float BN_EPS  = 1e-5f;
static constexpr float CNT_INV = 1.0f / (float)(B_ * N_);

// ---------------- device-global scratch (no cudaMalloc allowed) ---------------
__device__ __nv_bfloat16 g_xh[(size_t)B_ * N_ * K1_];   // concat input, bf16 hi
__device__ __nv_bfloat16 g_xl[(size_t)B_ * N_ * K1_];   // concat input, bf16 lo
__device__ float         g_y [(size_t)B_ * N_ * O_];    // y1 then y2 (n-major)
__device__ __nv_bfloat16 g_hh[(size_t)B_ * N_ * O_];    // layer2 input hi
__device__ __nv_bfloat16 g_hl[(size_t)B_ * N_ * O_];    // layer2 input lo
__device__ float         g_p2t[(size_t)B_ * S_ * C2_];  // points2 transposed [B][S][C]
__device__ int           g_idx[(size_t)B_ * N_ * 3];
__device__ float         g_w  [(size_t)B_ * N_ * 3];
__device__ __nv_bfloat16 g_w0h[O_ * K1_], g_w0l[O_ * K1_];
__device__ __nv_bfloat16 g_w1h[O_ * O_],  g_w1l[O_ * O_];
__device__ float         g_psum[256 * 1024], g_pssq[256 * 1024];
__device__ float         g_sb1[512], g_sb2[512];

// ---------------- small PTX helpers ------------------------------------------
__device__ __forceinline__ uint32_t smem_u32(const void* p) {
    uint32_t a;
    asm("{ .reg .u64 t; cvta.to.shared.u64 t, %1; cvt.u32.u64 %0, t; }"
        : "=r"(a) : "l"(p));
    return a;
}
__device__ __forceinline__ void cpa16(uint32_t dst, const void* src) {
    asm volatile("cp.async.cg.shared.global [%0], [%1], 16;"
                 :: "r"(dst), "l"(src) : "memory");
}
#define CP_COMMIT() asm volatile("cp.async.commit_group;" ::: "memory")
#define CP_WAIT0()  asm volatile("cp.async.wait_group 0;" ::: "memory")
#define CP_WAIT1()  asm volatile("cp.async.wait_group 1;" ::: "memory")

__device__ __forceinline__ void ldsm4(uint32_t addr, uint32_t* r) {
    asm volatile("ldmatrix.sync.aligned.m8n8.x4.shared.b16 {%0,%1,%2,%3}, [%4];"
                 : "=r"(r[0]), "=r"(r[1]), "=r"(r[2]), "=r"(r[3]) : "r"(addr));
}
__device__ __forceinline__ void mma16816(float* c, const uint32_t* a, const uint32_t* b) {
    asm volatile(
        "mma.sync.aligned.m16n8k16.row.col.f32.bf16.bf16.f32 "
        "{%0,%1,%2,%3}, {%4,%5,%6,%7}, {%8,%9}, {%0,%1,%2,%3};"
        : "+f"(c[0]), "+f"(c[1]), "+f"(c[2]), "+f"(c[3])
        : "r"(a[0]), "r"(a[1]), "r"(a[2]), "r"(a[3]), "r"(b[0]), "r"(b[1]));
}

// bf16 split helpers
__device__ __forceinline__ void bf16_split(float v, __nv_bfloat16& hi, __nv_bfloat16& lo) {
    hi = __float2bfloat16_rn(v);
    lo = __float2bfloat16_rn(v - __bfloat162float(hi));
}

// ---------------- kNN (4 queries per thread) ---------------------------------
__global__ __launch_bounds__(256) void knn_kernel(
    const float* __restrict__ xyz1, const float* __restrict__ xyz2)
{
    __shared__ float4 sp[S_];
    const int b = blockIdx.y;
    const int t = threadIdx.x;
    for (int s = t; s < S_; s += 256) {
        const float* p = xyz2 + ((size_t)b * S_ + s) * 3;
        sp[s] = make_float4(p[0], p[1], p[2], 0.0f);
    }
    __syncthreads();

    const int nb = blockIdx.x * 1024 + t;
    float qx[4], qy[4], qz[4];
    float d0[4], d1[4], d2[4];
    int   i0[4], i1[4], i2[4];
    #pragma unroll
    for (int j = 0; j < 4; j++) {
        const float* q = xyz1 + ((size_t)b * N_ + nb + j * 256) * 3;
        qx[j] = q[0]; qy[j] = q[1]; qz[j] = q[2];
        d0[j] = 3.4e38f; d1[j] = 3.4e38f; d2[j] = 3.4e38f;
        i0[j] = 0; i1[j] = 0; i2[j] = 0;
    }
    #pragma unroll 2
    for (int s = 0; s < S_; s++) {
        float4 p = sp[s];
        #pragma unroll
        for (int j = 0; j < 4; j++) {
            float dx = qx[j] - p.x, dy = qy[j] - p.y, dz = qz[j] - p.z;
            float d = fmaf(dz, dz, fmaf(dy, dy, dx * dx));
            if (d < d2[j]) {
                if (d < d1[j]) {
                    d2[j] = d1[j]; i2[j] = i1[j];
                    if (d < d0[j]) { d1[j] = d0[j]; i1[j] = i0[j]; d0[j] = d; i0[j] = s; }
                    else           { d1[j] = d;  i1[j] = s; }
                } else { d2[j] = d; i2[j] = s; }
            }
        }
    }
    #pragma unroll
    for (int j = 0; j < 4; j++) {
        float a = fmaxf(d0[j], 1e-10f), bb = fmaxf(d1[j], 1e-10f), c = fmaxf(d2[j], 1e-10f);
        float w0 = 1.0f / a, w1 = 1.0f / bb, w2 = 1.0f / c;
        float sw = w0 + w1 + w2;
        size_t base = ((size_t)b * N_ + nb + j * 256) * 3;
        g_idx[base] = i0[j]; g_idx[base + 1] = i1[j]; g_idx[base + 2] = i2[j];
        g_w[base] = w0 / sw; g_w[base + 1] = w1 / sw; g_w[base + 2] = w2 / sw;
    }
}

// ---------------- transpose points2 [B][C][S] -> [B][S][C] --------------------
__global__ void transpose_p2_kernel(const float* __restrict__ p2)
{
    __shared__ float tile[32][33];
    const int b  = blockIdx.z;
    const int s0 = blockIdx.x * 32;
    const int c0 = blockIdx.y * 32;
    #pragma unroll
    for (int r = 0; r < 4; r++) {
        int c = c0 + threadIdx.y + r * 8;
        tile[threadIdx.y + r * 8][threadIdx.x] =
            p2[((size_t)b * C2_ + c) * S_ + s0 + threadIdx.x];
    }
    __syncthreads();
    #pragma unroll
    for (int r = 0; r < 4; r++) {
        int s = s0 + threadIdx.y + r * 8;
        g_p2t[((size_t)b * S_ + s) * C2_ + c0 + threadIdx.x] =
            tile[threadIdx.x][threadIdx.y + r * 8];
    }
}

// ---------------- gather + weighted sum -> xcat channels [0,256) --------------
__global__ __launch_bounds__(256) void gather_kernel()
{
    const int b  = blockIdx.y;
    const int n0 = blockIdx.x * 32;
    const int t  = threadIdx.x;          // channel
    #pragma unroll 2
    for (int nl = 0; nl < 32; nl++) {
        size_t base = ((size_t)b * N_ + n0 + nl) * 3;
        int i0 = g_idx[base], i1 = g_idx[base + 1], i2 = g_idx[base + 2];
        float w0 = g_w[base], w1 = g_w[base + 1], w2 = g_w[base + 2];
        const float* r0 = g_p2t + ((size_t)b * S_ + i0) * C2_;
        const float* r1 = g_p2t + ((size_t)b * S_ + i1) * C2_;
        const float* r2 = g_p2t + ((size_t)b * S_ + i2) * C2_;
        float v = fmaf(w2, r2[t], fmaf(w1, r1[t], w0 * r0[t]));
        __nv_bfloat16 hi, lo; bf16_split(v, hi, lo);
        size_t o = ((size_t)b * N_ + n0 + nl) * K1_ + t;
        g_xh[o] = hi; g_xl[o] = lo;
    }
}

// ---------------- points1 transpose+split -> xcat channels [256,384) ----------
__global__ void p1t_kernel(const float* __restrict__ p1)
{
    __shared__ float tile[32][33];
    const int b  = blockIdx.z;
    const int n0 = blockIdx.x * 32;
    const int c0 = blockIdx.y * 32;
    #pragma unroll
    for (int r = 0; r < 4; r++) {
        int c = c0 + threadIdx.y + r * 8;
        tile[threadIdx.y + r * 8][threadIdx.x] =
            p1[((size_t)b * C1_ + c) * N_ + n0 + threadIdx.x];
    }
    __syncthreads();
    #pragma unroll
    for (int r = 0; r < 4; r++) {
        int n = n0 + threadIdx.y + r * 8;
        float v = tile[threadIdx.x][threadIdx.y + r * 8];
        __nv_bfloat16 hi, lo; bf16_split(v, hi, lo);
        size_t o = ((size_t)b * N_ + n) * K1_ + 256 + c0 + threadIdx.x;
        g_xh[o] = hi; g_xl[o] = lo;
    }
}

// ---------------- weight split -------------------------------------------------
__global__ void wsplit_kernel(const float* __restrict__ w,
                              __nv_bfloat16* __restrict__ hi,
                              __nv_bfloat16* __restrict__ lo, int n)
{
    int i = blockIdx.x * 256 + threadIdx.x;
    if (i < n) {
        __nv_bfloat16 h, l; bf16_split(w[i], h, l);
        hi[i] = h; lo[i] = l;
    }
}

// ---------------- mma.sync bf16 GEMM (3-term compensation, 16 warps) ----------
// CTA tile M=256 x N=128, 512 thr = 16 warps (4 in M x 4 in N), warp 64x32.
// Epilogue: smem-staged coalesced flush to Y (n-major) + BN partials.
template<int KDIM>
__global__ __launch_bounds__(512) void gemm_mma(
    const __nv_bfloat16* __restrict__ Ahi, const __nv_bfloat16* __restrict__ Alo,
    const __nv_bfloat16* __restrict__ Bhi, const __nv_bfloat16* __restrict__ Blo,
    const float* __restrict__ bias, float* __restrict__ Y,
    float* __restrict__ psum, float* __restrict__ pssq)
{
    constexpr int NS = KDIM / 32;                 // K stages of 32
    constexpr uint32_t PITCH  = 80;               // smem bytes/row: 64B data + 16B pad
    constexpr uint32_t OFF_AL = 256u * PITCH;     // 20480
    constexpr uint32_t OFF_BH = 2u * 256u * PITCH;// 40960
    constexpr uint32_t BVSZ   = 128u * PITCH;     // 10240
    constexpr uint32_t STAGE  = OFF_BH + 2u * BVSZ; // 61440

    extern __shared__ char sdyn[];
    __shared__ float sm_s[4][256], sm_q[4][256];

    const int tid  = threadIdx.x;
    const int lane = tid & 31, wid = tid >> 5;
    const int mw   = wid & 3;        // M block of 64
    const int nw   = wid >> 2;       // N block of 32
    const int b    = blockIdx.y;
    const int n0   = blockIdx.x * 128;
    const size_t bn0 = (size_t)b * N_ + n0;
    const uint32_t sb0 = smem_u32(sdyn);

    auto load_stage = [&](int kt, int buf) {
        uint32_t base = sb0 + (uint32_t)buf * STAGE;
        #pragma unroll
        for (int i = 0; i < 4; i++) {              // A: 2 var x 256 rows x 4 chunks
            int c = tid + i * 512;
            int var = c >> 10, row = (c >> 2) & 255, ch = c & 3;
            const __nv_bfloat16* src = (var ? Alo : Ahi)
                + (size_t)row * KDIM + kt + ch * 8;
            cpa16(base + (uint32_t)var * OFF_AL + (uint32_t)row * PITCH + ch * 16, src);
        }
        #pragma unroll
        for (int i = 0; i < 2; i++) {              // B: 2 var x 128 rows x 4 chunks
            int c = tid + i * 512;
            int var = c >> 9, row = (c >> 2) & 127, ch = c & 3;
            const __nv_bfloat16* src = (var ? Blo : Bhi)
                + (bn0 + row) * KDIM + kt + ch * 8;
            cpa16(base + OFF_BH + (uint32_t)var * BVSZ + (uint32_t)row * PITCH + ch * 16, src);
        }
        CP_COMMIT();
    };

    float acc[4][4][4] = {};

    load_stage(0, 0);

    #pragma unroll 1
    for (int s = 0; s < NS; s++) {
        if (s + 1 < NS) { load_stage((s + 1) * 32, (s + 1) & 1); CP_WAIT1(); }
        else            { CP_WAIT0(); }
        __syncthreads();

        uint32_t base = sb0 + (uint32_t)(s & 1) * STAGE;
        #pragma unroll
        for (int ks = 0; ks < 2; ks++) {
            // B fragments, both variants (hi/lo), 32 n-rows
            uint32_t bb[2][2][4];
            #pragma unroll
            for (int var = 0; var < 2; var++)
                #pragma unroll
                for (int pair = 0; pair < 2; pair++) {
                    uint32_t rowB = (uint32_t)(nw * 32 + pair * 16
                                   + ((lane >> 4) << 3) + (lane & 7));
                    ldsm4(base + OFF_BH + (uint32_t)var * BVSZ + rowB * PITCH
                          + ks * 32 + (((lane >> 3) & 1) << 4), bb[var][pair]);
                }
            uint32_t a[4][4];
            // A-hi fragments
            #pragma unroll
            for (int mt = 0; mt < 4; mt++) {
                uint32_t row = (uint32_t)(mw * 64 + mt * 16 + (lane & 15));
                ldsm4(base + row * PITCH + ks * 32 + ((lane >> 4) << 4), a[mt]);
            }
            // hh term + hi*lo term (A-hi reused)
            #pragma unroll
            for (int nt = 0; nt < 4; nt++) {
                const uint32_t* bh = &bb[0][nt >> 1][(nt & 1) * 2];
                const uint32_t* bl = &bb[1][nt >> 1][(nt & 1) * 2];
                #pragma unroll
                for (int mt = 0; mt < 4; mt++) {
                    mma16816(acc[mt][nt], a[mt], bh);
                    mma16816(acc[mt][nt], a[mt], bl);
                }
            }
            // A-lo fragments (overwrite a[]), lo*hi term
            #pragma unroll
            for (int mt = 0; mt < 4; mt++) {
                uint32_t row = (uint32_t)(mw * 64 + mt * 16 + (lane & 15));
                ldsm4(base + OFF_AL + row * PITCH + ks * 32 + ((lane >> 4) << 4), a[mt]);
            }
            #pragma unroll
            for (int nt = 0; nt < 4; nt++) {
                const uint32_t* bh = &bb[0][nt >> 1][(nt & 1) * 2];
                #pragma unroll
                for (int mt = 0; mt < 4; mt++)
                    mma16816(acc[mt][nt], a[mt], bh);
            }
        }
        __syncthreads();
    }

    // ---- epilogue: bias, BN partials, smem-staged coalesced flush ------------
    float* sy = (float*)sdyn;             // [64][260] per half
    const int r = lane >> 2;
    float csum[8] = {}, cssq[8] = {};

    #pragma unroll
    for (int half = 0; half < 2; half++) {
        if ((nw >> 1) == half) {
            #pragma unroll
            for (int mt = 0; mt < 4; mt++) {
                const int m0 = mw * 64 + mt * 16 + r;
                const int m1 = m0 + 8;
                const float bv0 = bias[m0], bv1 = bias[m1];
                #pragma unroll
                for (int nt = 0; nt < 4; nt++) {
                    float* c = acc[mt][nt];
                    int nl = (nw & 1) * 32 + nt * 8 + (lane & 3) * 2;
                    float v0 = c[0] + bv0, v1 = c[1] + bv0;
                    float v2 = c[2] + bv1, v3 = c[3] + bv1;
                    sy[nl * 260 + m0]       = v0;
                    sy[(nl + 1) * 260 + m0] = v1;
                    sy[nl * 260 + m1]       = v2;
                    sy[(nl + 1) * 260 + m1] = v3;
                    csum[mt * 2]     += v0 + v1;
                    cssq[mt * 2]     += fmaf(v0, v0, v1 * v1);
                    csum[mt * 2 + 1] += v2 + v3;
                    cssq[mt * 2 + 1] += fmaf(v2, v2, v3 * v3);
                }
            }
        }
        __syncthreads();
        // coalesced flush: 64 rows x 1KB
        #pragma unroll 4
        for (int i = 0; i < 32; i++) {
            int row = i * 2 + (tid >> 8);
            Y[(bn0 + half * 64 + row) * 256 + (tid & 255)] = sy[row * 260 + (tid & 255)];
        }
        __syncthreads();
    }

    // BN partials
    #pragma unroll
    for (int j = 0; j < 8; j++) {
        csum[j] += __shfl_xor_sync(0xffffffffu, csum[j], 1);
        csum[j] += __shfl_xor_sync(0xffffffffu, csum[j], 2);
        cssq[j] += __shfl_xor_sync(0xffffffffu, cssq[j], 1);
        cssq[j] += __shfl_xor_sync(0xffffffffu, cssq[j], 2);
    }
    if ((lane & 3) == 0) {
        #pragma unroll
        for (int mt = 0; mt < 4; mt++) {
            #pragma unroll
            for (int h = 0; h < 2; h++) {
                int ch = mw * 64 + mt * 16 + r + h * 8;
                sm_s[nw][ch] = csum[mt * 2 + h];
                sm_q[nw][ch] = cssq[mt * 2 + h];
            }
        }
    }
    __syncthreads();
    if (tid < 256) {
        int cta = blockIdx.x + blockIdx.y * gridDim.x;
        psum[tid * 1024 + cta] = sm_s[0][tid] + sm_s[1][tid] + sm_s[2][tid] + sm_s[3][tid];
        pssq[tid * 1024 + cta] = sm_q[0][tid] + sm_q[1][tid] + sm_q[2][tid] + sm_q[3][tid];
    }
}

// ---------------- BN fold: reduce 1024 partials per channel -------------------
__global__ __launch_bounds__(256) void stats2_kernel(
    const float* __restrict__ g, const float* __restrict__ beta,
    float* __restrict__ sb)
{
    const int o = blockIdx.x;
    const int t = threadIdx.x;
    float s = 0.0f, ss = 0.0f;
    #pragma unroll
    for (int i = 0; i < 4; i++) {
        s  += g_psum[o * 1024 + t * 4 + i];
        ss += g_pssq[o * 1024 + t * 4 + i];
    }
    const int lane = t & 31, w = t >> 5;
    #pragma unroll
    for (int off = 16; off; off >>= 1) {
        s  += __shfl_down_sync(0xffffffffu, s,  off);
        ss += __shfl_down_sync(0xffffffffu, ss, off);
    }
    __shared__ float rs[8], rss[8];
    if (lane == 0) { rs[w] = s; rss[w] = ss; }
    __syncthreads();
    if (t == 0) {
        float ts = 0.0f, tss = 0.0f;
        #pragma unroll
        for (int i = 0; i < 8; i++) { ts += rs[i]; tss += rss[i]; }
        float mean = ts * CNT_INV;
        float var  = tss * CNT_INV - mean * mean;
        float rstd = rsqrtf(var + BN_EPS);
        float sc = g[o] * rstd;
        sb[o]       = sc;
        sb[256 + o] = beta[o] - mean * sc;
    }
}

// ---------------- layer-1 norm + relu + bf16 split -> h -----------------------
__global__ __launch_bounds__(256) void splith_kernel(
    const float* __restrict__ y, const float* __restrict__ sb)
{
    size_t i4 = (size_t)blockIdx.x * 256 + threadIdx.x;   // over B*N*64
    int c4 = (int)(i4 & 63) * 4;
    float4 v  = ((const float4*)y)[i4];
    float4 sc = *(const float4*)(sb + c4);
    float4 bs = *(const float4*)(sb + 256 + c4);
    float a0 = fmaxf(fmaf(v.x, sc.x, bs.x), 0.0f);
    float a1 = fmaxf(fmaf(v.y, sc.y, bs.y), 0.0f);
    float a2 = fmaxf(fmaf(v.z, sc.z, bs.z), 0.0f);
    float a3 = fmaxf(fmaf(v.w, sc.w, bs.w), 0.0f);
    __nv_bfloat16 h0, l0, h1, l1, h2, l2, h3, l3;
    bf16_split(a0, h0, l0); bf16_split(a1, h1, l1);
    bf16_split(a2, h2, l2); bf16_split(a3, h3, l3);
    uint2 ph, pl;
    ph.x = (uint32_t)__bfloat16_as_ushort(h0) | ((uint32_t)__bfloat16_as_ushort(h1) << 16);
    ph.y = (uint32_t)__bfloat16_as_ushort(h2) | ((uint32_t)__bfloat16_as_ushort(h3) << 16);
    pl.x = (uint32_t)__bfloat16_as_ushort(l0) | ((uint32_t)__bfloat16_as_ushort(l1) << 16);
    pl.y = (uint32_t)__bfloat16_as_ushort(l2) | ((uint32_t)__bfloat16_as_ushort(l3) << 16);
    ((uint2*)g_hh)[i4] = ph;
    ((uint2*)g_hl)[i4] = pl;
}

// ---------------- final norm + relu + transpose -> out [B][256][N] ------------
__global__ __launch_bounds__(256) void outt_kernel(
    const float* __restrict__ y, const float* __restrict__ sb,
    float* __restrict__ out)
{
    __shared__ float tile[32][33];
    const int b  = blockIdx.z;
    const int n0 = blockIdx.x * 32;
    const int m0 = blockIdx.y * 32;
    const float sc = sb[m0 + threadIdx.x];
    const float bs = sb[256 + m0 + threadIdx.x];
    #pragma unroll
    for (int r = 0; r < 4; r++) {
        int n = n0 + threadIdx.y + r * 8;
        float v = y[((size_t)b * N_ + n) * 256 + m0 + threadIdx.x];
        tile[threadIdx.y + r * 8][threadIdx.x] = fmaxf(fmaf(v, sc, bs), 0.0f);
    }
    __syncthreads();
    #pragma unroll
    for (int r = 0; r < 4; r++) {
        int m = m0 + threadIdx.y + r * 8;
        out[((size_t)b * 256 + m) * N_ + n0 + threadIdx.x] =
            tile[threadIdx.x][threadIdx.y + r * 8];
    }
}

// ---------------- launcher ----------------------------------------------------
extern "C" void kernel_launch(void* const* d_in, const int* in_sizes, int n_in,
                              void* d_out, int out_size)
{
    const float* xyz1 = (const float*)d_in[0];
    const float* xyz2 = (const float*)d_in[1];
    const float* pts1 = (const float*)d_in[2];
    const float* pts2 = (const float*)d_in[3];
    const float* W0   = (const float*)d_in[4];
    const float* b0   = (const float*)d_in[5];
    const float* gg0  = (const float*)d_in[6];
    const float* be0  = (const float*)d_in[7];
    const float* W1   = (const float*)d_in[8];
    const float* b1   = (const float*)d_in[9];
    const float* gg1  = (const float*)d_in[10];
    const float* be1  = (const float*)d_in[11];
    float* out = (float*)d_out;

    __nv_bfloat16 *xh, *xl, *hh, *hl, *w0h, *w0l, *w1h, *w1l;
    float *y, *psum, *pssq, *sb1, *sb2;
    cudaGetSymbolAddress((void**)&xh,  g_xh);
    cudaGetSymbolAddress((void**)&xl,  g_xl);
    cudaGetSymbolAddress((void**)&hh,  g_hh);
    cudaGetSymbolAddress((void**)&hl,  g_hl);
    cudaGetSymbolAddress((void**)&w0h, g_w0h);
    cudaGetSymbolAddress((void**)&w0l, g_w0l);
    cudaGetSymbolAddress((void**)&w1h, g_w1h);
    cudaGetSymbolAddress((void**)&w1l, g_w1l);
    cudaGetSymbolAddress((void**)&y,   g_y);
    cudaGetSymbolAddress((void**)&psum, g_psum);
    cudaGetSymbolAddress((void**)&pssq, g_pssq);
    cudaGetSymbolAddress((void**)&sb1, g_sb1);
    cudaGetSymbolAddress((void**)&sb2, g_sb2);

    const int GEMM_SMEM = 2 * 61440;   // 120 KB double-buffered stages
    cudaFuncSetAttribute(gemm_mma<K1_>, cudaFuncAttributeMaxDynamicSharedMemorySize, GEMM_SMEM);
    cudaFuncSetAttribute(gemm_mma<O_>,  cudaFuncAttributeMaxDynamicSharedMemorySize, GEMM_SMEM);

    // prep
    wsplit_kernel<<<(O_ * K1_ + 255) / 256, 256>>>(W0, w0h, w0l, O_ * K1_);
    wsplit_kernel<<<(O_ * O_  + 255) / 256, 256>>>(W1, w1h, w1l, O_ * O_);
    knn_kernel<<<dim3(N_ / 1024, B_), 256>>>(xyz1, xyz2);
    transpose_p2_kernel<<<dim3(S_ / 32, C2_ / 32, B_), dim3(32, 8)>>>(pts2);
    gather_kernel<<<dim3(N_ / 32, B_), 256>>>();
    p1t_kernel<<<dim3(N_ / 32, C1_ / 32, B_), dim3(32, 8)>>>(pts1);

    // layer 1
    gemm_mma<K1_><<<dim3(N_ / 128, B_), 512, GEMM_SMEM>>>(w0h, w0l, xh, xl, b0, y, psum, pssq);
    stats2_kernel<<<256, 256>>>(gg0, be0, sb1);
    splith_kernel<<<(int)((size_t)B_ * N_ * 64 / 256), 256>>>(y, sb1);

    // layer 2
    gemm_mma<O_><<<dim3(N_ / 128, B_), 512, GEMM_SMEM>>>(w1h, w1l, hh, hl, b1, y, psum, pssq);
    stats2_kernel<<<256, 256>>>(gg1, be1, sb2);

    // output
    outt_kernel<<<dim3(N_ / 32, 8, B_), dim3(32, 8)>>>(y, sb2, out);
}

// round 6
// speedup vs baseline: 1.8906x; 1.1370x over previous
#include <cuda_runtime.h>
#include <cuda_fp16.h>
#include <cstdint>

static constexpr int B_  = 8;
static constexpr int N_  = 16384;
static constexpr int S_  = 2048;
static constexpr int C1_ = 128;
static constexpr int C2_ = 256;
static constexpr int K1_ = 384;
static constexpr int O_  = 256;
static constexpr float BN_EPS  = 1e-5f;
static constexpr float CNT_INV = 1.0f / (float)(B_ * N_);
static constexpr float WSCALE   = 64.0f;        // exact pow2 pre-scale for W split
static constexpr float WSCALE_I = 1.0f / 64.0f;

// ---------------- device-global scratch (no cudaMalloc allowed) ---------------
__device__ __half g_xq[(size_t)B_ * N_ * K1_];   // concat input, fp16 [n][k]
__device__ float  g_y [(size_t)B_ * N_ * O_];    // y1 then y2 (n-major)
__device__ __half g_hq[(size_t)B_ * N_ * O_];    // layer2 input fp16
__device__ float  g_p2t[(size_t)B_ * S_ * C2_];  // points2 transposed [B][S][C]
__device__ int    g_idx[(size_t)B_ * N_ * 3];
__device__ float  g_w  [(size_t)B_ * N_ * 3];
__device__ __half g_w0h[O_ * K1_], g_w0l[O_ * K1_];   // W*64 split hi/lo
__device__ __half g_w1h[O_ * O_],  g_w1l[O_ * O_];
__device__ float  g_psum[256 * 1024], g_pssq[256 * 1024];
__device__ float  g_sb1[512], g_sb2[512];

// ---------------- small PTX helpers ------------------------------------------
__device__ __forceinline__ uint32_t smem_u32(const void* p) {
    uint32_t a;
    asm("{ .reg .u64 t; cvta.to.shared.u64 t, %1; cvt.u32.u64 %0, t; }"
        : "=r"(a) : "l"(p));
    return a;
}
__device__ __forceinline__ void cpa16(uint32_t dst, const void* src) {
    asm volatile("cp.async.cg.shared.global [%0], [%1], 16;"
                 :: "r"(dst), "l"(src) : "memory");
}
#define CP_COMMIT() asm volatile("cp.async.commit_group;" ::: "memory")
#define CP_WAIT0()  asm volatile("cp.async.wait_group 0;" ::: "memory")
#define CP_WAIT1()  asm volatile("cp.async.wait_group 1;" ::: "memory")

__device__ __forceinline__ void ldsm4(uint32_t addr, uint32_t* r) {
    asm volatile("ldmatrix.sync.aligned.m8n8.x4.shared.b16 {%0,%1,%2,%3}, [%4];"
                 : "=r"(r[0]), "=r"(r[1]), "=r"(r[2]), "=r"(r[3]) : "r"(addr));
}
__device__ __forceinline__ void mma16816(float* c, const uint32_t* a, const uint32_t* b) {
    asm volatile(
        "mma.sync.aligned.m16n8k16.row.col.f32.f16.f16.f32 "
        "{%0,%1,%2,%3}, {%4,%5,%6,%7}, {%8,%9}, {%0,%1,%2,%3};"
        : "+f"(c[0]), "+f"(c[1]), "+f"(c[2]), "+f"(c[3])
        : "r"(a[0]), "r"(a[1]), "r"(a[2]), "r"(a[3]), "r"(b[0]), "r"(b[1]));
}

// fp16 split (applied to pre-scaled values so lo stays normal)
__device__ __forceinline__ void h_split(float v, __half& hi, __half& lo) {
    hi = __float2half_rn(v);
    lo = __float2half_rn(v - __half2float(hi));
}

// ---------------- kNN (4 queries per thread) ---------------------------------
__global__ __launch_bounds__(256) void knn_kernel(
    const float* __restrict__ xyz1, const float* __restrict__ xyz2)
{
    __shared__ float4 sp[S_];
    const int b = blockIdx.y;
    const int t = threadIdx.x;
    for (int s = t; s < S_; s += 256) {
        const float* p = xyz2 + ((size_t)b * S_ + s) * 3;
        sp[s] = make_float4(p[0], p[1], p[2], 0.0f);
    }
    __syncthreads();

    const int nb = blockIdx.x * 1024 + t;
    float qx[4], qy[4], qz[4];
    float d0[4], d1[4], d2[4];
    int   i0[4], i1[4], i2[4];
    #pragma unroll
    for (int j = 0; j < 4; j++) {
        const float* q = xyz1 + ((size_t)b * N_ + nb + j * 256) * 3;
        qx[j] = q[0]; qy[j] = q[1]; qz[j] = q[2];
        d0[j] = 3.4e38f; d1[j] = 3.4e38f; d2[j] = 3.4e38f;
        i0[j] = 0; i1[j] = 0; i2[j] = 0;
    }
    #pragma unroll 2
    for (int s = 0; s < S_; s++) {
        float4 p = sp[s];
        #pragma unroll
        for (int j = 0; j < 4; j++) {
            float dx = qx[j] - p.x, dy = qy[j] - p.y, dz = qz[j] - p.z;
            float d = fmaf(dz, dz, fmaf(dy, dy, dx * dx));
            if (d < d2[j]) {
                if (d < d1[j]) {
                    d2[j] = d1[j]; i2[j] = i1[j];
                    if (d < d0[j]) { d1[j] = d0[j]; i1[j] = i0[j]; d0[j] = d; i0[j] = s; }
                    else           { d1[j] = d;  i1[j] = s; }
                } else { d2[j] = d; i2[j] = s; }
            }
        }
    }
    #pragma unroll
    for (int j = 0; j < 4; j++) {
        float a = fmaxf(d0[j], 1e-10f), bb = fmaxf(d1[j], 1e-10f), c = fmaxf(d2[j], 1e-10f);
        float w0 = 1.0f / a, w1 = 1.0f / bb, w2 = 1.0f / c;
        float sw = w0 + w1 + w2;
        size_t base = ((size_t)b * N_ + nb + j * 256) * 3;
        g_idx[base] = i0[j]; g_idx[base + 1] = i1[j]; g_idx[base + 2] = i2[j];
        g_w[base] = w0 / sw; g_w[base + 1] = w1 / sw; g_w[base + 2] = w2 / sw;
    }
}

// ---------------- transpose points2 [B][C][S] -> [B][S][C] --------------------
__global__ void transpose_p2_kernel(const float* __restrict__ p2)
{
    __shared__ float tile[32][33];
    const int b  = blockIdx.z;
    const int s0 = blockIdx.x * 32;
    const int c0 = blockIdx.y * 32;
    #pragma unroll
    for (int r = 0; r < 4; r++) {
        int c = c0 + threadIdx.y + r * 8;
        tile[threadIdx.y + r * 8][threadIdx.x] =
            p2[((size_t)b * C2_ + c) * S_ + s0 + threadIdx.x];
    }
    __syncthreads();
    #pragma unroll
    for (int r = 0; r < 4; r++) {
        int s = s0 + threadIdx.y + r * 8;
        g_p2t[((size_t)b * S_ + s) * C2_ + c0 + threadIdx.x] =
            tile[threadIdx.x][threadIdx.y + r * 8];
    }
}

// ---------------- gather + weighted sum -> xcat channels [0,256) --------------
__global__ __launch_bounds__(256) void gather_kernel()
{
    const int b  = blockIdx.y;
    const int n0 = blockIdx.x * 32;
    const int t  = threadIdx.x;          // channel
    #pragma unroll 2
    for (int nl = 0; nl < 32; nl++) {
        size_t base = ((size_t)b * N_ + n0 + nl) * 3;
        int i0 = g_idx[base], i1 = g_idx[base + 1], i2 = g_idx[base + 2];
        float w0 = g_w[base], w1 = g_w[base + 1], w2 = g_w[base + 2];
        const float* r0 = g_p2t + ((size_t)b * S_ + i0) * C2_;
        const float* r1 = g_p2t + ((size_t)b * S_ + i1) * C2_;
        const float* r2 = g_p2t + ((size_t)b * S_ + i2) * C2_;
        float v = fmaf(w2, r2[t], fmaf(w1, r1[t], w0 * r0[t]));
        g_xq[((size_t)b * N_ + n0 + nl) * K1_ + t] = __float2half_rn(v);
    }
}

// ---------------- points1 transpose -> xcat channels [256,384) ----------------
__global__ void p1t_kernel(const float* __restrict__ p1)
{
    __shared__ float tile[32][33];
    const int b  = blockIdx.z;
    const int n0 = blockIdx.x * 32;
    const int c0 = blockIdx.y * 32;
    #pragma unroll
    for (int r = 0; r < 4; r++) {
        int c = c0 + threadIdx.y + r * 8;
        tile[threadIdx.y + r * 8][threadIdx.x] =
            p1[((size_t)b * C1_ + c) * N_ + n0 + threadIdx.x];
    }
    __syncthreads();
    #pragma unroll
    for (int r = 0; r < 4; r++) {
        int n = n0 + threadIdx.y + r * 8;
        float v = tile[threadIdx.x][threadIdx.y + r * 8];
        g_xq[((size_t)b * N_ + n) * K1_ + 256 + c0 + threadIdx.x] = __float2half_rn(v);
    }
}

// ---------------- weight split: (W*64) -> fp16 hi + lo ------------------------
__global__ void wsplit_kernel(const float* __restrict__ w,
                              __half* __restrict__ hi,
                              __half* __restrict__ lo, int n)
{
    int i = blockIdx.x * 256 + threadIdx.x;
    if (i < n) {
        __half h, l; h_split(w[i] * WSCALE, h, l);
        hi[i] = h; lo[i] = l;
    }
}

// ---------------- mma.sync fp16 GEMM (2-term weight compensation) -------------
// D[m 0..255][n tile 128] = sum_k (Whi+Wlo)[m][k]*X[n][k] / 64; X single fp16.
// CTA: 256 thr = 8 warps (4 in M x 2 in N). Warp tile 64x64.
// Epilogue: smem-staged coalesced flush to Y (n-major) + BN partials.
template<int KDIM>
__global__ __launch_bounds__(256) void gemm_mma(
    const __half* __restrict__ Ahi, const __half* __restrict__ Alo,
    const __half* __restrict__ Bq,
    const float* __restrict__ bias, float* __restrict__ Y,
    float* __restrict__ psum, float* __restrict__ pssq)
{
    constexpr int NS = KDIM / 32;                 // K stages of 32
    constexpr uint32_t PITCH  = 80;               // 64B data + 16B pad
    constexpr uint32_t OFF_AL = 256u * PITCH;     // 20480
    constexpr uint32_t OFF_B  = 2u * OFF_AL;      // 40960
    constexpr uint32_t STAGE  = OFF_B + 128u * PITCH;  // 51200

    extern __shared__ char sdyn[];
    __shared__ float sm_s[2][256], sm_q[2][256];

    const int tid  = threadIdx.x;
    const int lane = tid & 31, wid = tid >> 5;
    const int mw   = wid & 3;        // M block of 64
    const int nw   = wid >> 2;       // N block of 64
    const int b    = blockIdx.y;
    const int n0   = blockIdx.x * 128;
    const size_t bn0 = (size_t)b * N_ + n0;
    const uint32_t sb0 = smem_u32(sdyn);

    auto load_stage = [&](int kt, int buf) {
        uint32_t base = sb0 + (uint32_t)buf * STAGE;
        #pragma unroll
        for (int i = 0; i < 8; i++) {              // A: 2 var x 256 rows x 4 chunks
            int c = tid + i * 256;
            int var = c >> 10, row = (c >> 2) & 255, ch = c & 3;
            const __half* src = (var ? Alo : Ahi) + (size_t)row * KDIM + kt + ch * 8;
            cpa16(base + (uint32_t)var * OFF_AL + (uint32_t)row * PITCH + ch * 16, src);
        }
        #pragma unroll
        for (int i = 0; i < 2; i++) {              // B: 128 rows x 4 chunks
            int c = tid + i * 256;
            int row = (c >> 2) & 127, ch = c & 3;
            const __half* src = Bq + (bn0 + row) * KDIM + kt + ch * 8;
            cpa16(base + OFF_B + (uint32_t)row * PITCH + ch * 16, src);
        }
        CP_COMMIT();
    };

    float acc[4][8][4] = {};

    load_stage(0, 0);

    #pragma unroll 1
    for (int s = 0; s < NS; s++) {
        if (s + 1 < NS) { load_stage((s + 1) * 32, (s + 1) & 1); CP_WAIT1(); }
        else            { CP_WAIT0(); }
        __syncthreads();

        uint32_t base = sb0 + (uint32_t)(s & 1) * STAGE;
        #pragma unroll
        for (int ks = 0; ks < 2; ks++) {
            uint32_t a[2][4][4];
            #pragma unroll
            for (int var = 0; var < 2; var++)
                #pragma unroll
                for (int mt = 0; mt < 4; mt++) {
                    uint32_t row = (uint32_t)(mw * 64 + mt * 16 + (lane & 15));
                    ldsm4(base + (uint32_t)var * OFF_AL + row * PITCH
                          + ks * 32 + ((lane >> 4) << 4), a[var][mt]);
                }
            #pragma unroll
            for (int ntp = 0; ntp < 4; ntp++) {
                uint32_t rowB = (uint32_t)(nw * 64 + ntp * 16
                               + ((lane >> 4) << 3) + (lane & 7));
                uint32_t bfr[4];
                ldsm4(base + OFF_B + rowB * PITCH
                      + ks * 32 + (((lane >> 3) & 1) << 4), bfr);
                #pragma unroll
                for (int h = 0; h < 2; h++) {
                    int nt = ntp * 2 + h;
                    #pragma unroll
                    for (int mt = 0; mt < 4; mt++) {
                        mma16816(acc[mt][nt], a[0][mt], &bfr[h * 2]);
                        mma16816(acc[mt][nt], a[1][mt], &bfr[h * 2]);
                    }
                }
            }
        }
        __syncthreads();
    }

    // ---- epilogue: unscale, bias, BN partials, smem-staged coalesced flush ---
    float* sy = (float*)sdyn;             // [64][260] per N-half
    const int r = lane >> 2;
    float csum[8] = {}, cssq[8] = {};

    #pragma unroll
    for (int half = 0; half < 2; half++) {
        if (nw == half) {
            #pragma unroll
            for (int mt = 0; mt < 4; mt++) {
                const int m0 = mw * 64 + mt * 16 + r;
                const int m1 = m0 + 8;
                const float bv0 = bias[m0], bv1 = bias[m1];
                #pragma unroll
                for (int nt = 0; nt < 8; nt++) {
                    float* c = acc[mt][nt];
                    int nl = nt * 8 + (lane & 3) * 2;
                    float v0 = fmaf(c[0], WSCALE_I, bv0);
                    float v1 = fmaf(c[1], WSCALE_I, bv0);
                    float v2 = fmaf(c[2], WSCALE_I, bv1);
                    float v3 = fmaf(c[3], WSCALE_I, bv1);
                    sy[nl * 260 + m0]       = v0;
                    sy[(nl + 1) * 260 + m0] = v1;
                    sy[nl * 260 + m1]       = v2;
                    sy[(nl + 1) * 260 + m1] = v3;
                    csum[mt * 2]     += v0 + v1;
                    cssq[mt * 2]     += fmaf(v0, v0, v1 * v1);
                    csum[mt * 2 + 1] += v2 + v3;
                    cssq[mt * 2 + 1] += fmaf(v2, v2, v3 * v3);
                }
            }
        }
        __syncthreads();
        // coalesced flush: 64 rows x 1KB
        #pragma unroll 8
        for (int row = 0; row < 64; row++)
            Y[(bn0 + half * 64 + row) * 256 + tid] = sy[row * 260 + tid];
        __syncthreads();
    }

    // BN partials
    #pragma unroll
    for (int j = 0; j < 8; j++) {
        csum[j] += __shfl_xor_sync(0xffffffffu, csum[j], 1);
        csum[j] += __shfl_xor_sync(0xffffffffu, csum[j], 2);
        cssq[j] += __shfl_xor_sync(0xffffffffu, cssq[j], 1);
        cssq[j] += __shfl_xor_sync(0xffffffffu, cssq[j], 2);
    }
    if ((lane & 3) == 0) {
        #pragma unroll
        for (int mt = 0; mt < 4; mt++) {
            #pragma unroll
            for (int h = 0; h < 2; h++) {
                int ch = mw * 64 + mt * 16 + r + h * 8;
                sm_s[nw][ch] = csum[mt * 2 + h];
                sm_q[nw][ch] = cssq[mt * 2 + h];
            }
        }
    }
    __syncthreads();
    {
        int cta = blockIdx.x + blockIdx.y * gridDim.x;
        psum[tid * 1024 + cta] = sm_s[0][tid] + sm_s[1][tid];
        pssq[tid * 1024 + cta] = sm_q[0][tid] + sm_q[1][tid];
    }
}

// ---------------- BN fold: reduce 1024 partials per channel -------------------
__global__ __launch_bounds__(256) void stats2_kernel(
    const float* __restrict__ g, const float* __restrict__ beta,
    float* __restrict__ sb)
{
    const int o = blockIdx.x;
    const int t = threadIdx.x;
    float s = 0.0f, ss = 0.0f;
    #pragma unroll
    for (int i = 0; i < 4; i++) {
        s  += g_psum[o * 1024 + t * 4 + i];
        ss += g_pssq[o * 1024 + t * 4 + i];
    }
    const int lane = t & 31, w = t >> 5;
    #pragma unroll
    for (int off = 16; off; off >>= 1) {
        s  += __shfl_down_sync(0xffffffffu, s,  off);
        ss += __shfl_down_sync(0xffffffffu, ss, off);
    }
    __shared__ float rs[8], rss[8];
    if (lane == 0) { rs[w] = s; rss[w] = ss; }
    __syncthreads();
    if (t == 0) {
        float ts = 0.0f, tss = 0.0f;
        #pragma unroll
        for (int i = 0; i < 8; i++) { ts += rs[i]; tss += rss[i]; }
        float mean = ts * CNT_INV;
        float var  = tss * CNT_INV - mean * mean;
        float rstd = rsqrtf(var + BN_EPS);
        float sc = g[o] * rstd;
        sb[o]       = sc;
        sb[256 + o] = beta[o] - mean * sc;
    }
}

// ---------------- layer-1 norm + relu + fp16 quantize -> h --------------------
__global__ __launch_bounds__(256) void splitq_kernel(
    const float* __restrict__ y, const float* __restrict__ sb)
{
    size_t i4 = (size_t)blockIdx.x * 256 + threadIdx.x;   // over B*N*64
    int c4 = (int)(i4 & 63) * 4;
    float4 v  = ((const float4*)y)[i4];
    float4 sc = *(const float4*)(sb + c4);
    float4 bs = *(const float4*)(sb + 256 + c4);
    float a0 = fmaxf(fmaf(v.x, sc.x, bs.x), 0.0f);
    float a1 = fmaxf(fmaf(v.y, sc.y, bs.y), 0.0f);
    float a2 = fmaxf(fmaf(v.z, sc.z, bs.z), 0.0f);
    float a3 = fmaxf(fmaf(v.w, sc.w, bs.w), 0.0f);
    uint2 p;
    __half h0 = __float2half_rn(a0), h1 = __float2half_rn(a1);
    __half h2 = __float2half_rn(a2), h3 = __float2half_rn(a3);
    p.x = (uint32_t)__half_as_ushort(h0) | ((uint32_t)__half_as_ushort(h1) << 16);
    p.y = (uint32_t)__half_as_ushort(h2) | ((uint32_t)__half_as_ushort(h3) << 16);
    ((uint2*)g_hq)[i4] = p;
}

// ---------------- final norm + relu + transpose -> out [B][256][N] ------------
__global__ __launch_bounds__(256) void outt_kernel(
    const float* __restrict__ y, const float* __restrict__ sb,
    float* __restrict__ out)
{
    __shared__ float tile[32][33];
    const int b  = blockIdx.z;
    const int n0 = blockIdx.x * 32;
    const int m0 = blockIdx.y * 32;
    const float sc = sb[m0 + threadIdx.x];
    const float bs = sb[256 + m0 + threadIdx.x];
    #pragma unroll
    for (int r = 0; r < 4; r++) {
        int n = n0 + threadIdx.y + r * 8;
        float v = y[((size_t)b * N_ + n) * 256 + m0 + threadIdx.x];
        tile[threadIdx.y + r * 8][threadIdx.x] = fmaxf(fmaf(v, sc, bs), 0.0f);
    }
    __syncthreads();
    #pragma unroll
    for (int r = 0; r < 4; r++) {
        int m = m0 + threadIdx.y + r * 8;
        out[((size_t)b * 256 + m) * N_ + n0 + threadIdx.x] =
            tile[threadIdx.x][threadIdx.y + r * 8];
    }
}

// ---------------- launcher ----------------------------------------------------
extern "C" void kernel_launch(void* const* d_in, const int* in_sizes, int n_in,
                              void* d_out, int out_size)
{
    const float* xyz1 = (const float*)d_in[0];
    const float* xyz2 = (const float*)d_in[1];
    const float* pts1 = (const float*)d_in[2];
    const float* pts2 = (const float*)d_in[3];
    const float* W0   = (const float*)d_in[4];
    const float* b0   = (const float*)d_in[5];
    const float* gg0  = (const float*)d_in[6];
    const float* be0  = (const float*)d_in[7];
    const float* W1   = (const float*)d_in[8];
    const float* b1   = (const float*)d_in[9];
    const float* gg1  = (const float*)d_in[10];
    const float* be1  = (const float*)d_in[11];
    float* out = (float*)d_out;

    __half *xq, *hq, *w0h, *w0l, *w1h, *w1l;
    float *y, *psum, *pssq, *sb1, *sb2;
    cudaGetSymbolAddress((void**)&xq,  g_xq);
    cudaGetSymbolAddress((void**)&hq,  g_hq);
    cudaGetSymbolAddress((void**)&w0h, g_w0h);
    cudaGetSymbolAddress((void**)&w0l, g_w0l);
    cudaGetSymbolAddress((void**)&w1h, g_w1h);
    cudaGetSymbolAddress((void**)&w1l, g_w1l);
    cudaGetSymbolAddress((void**)&y,   g_y);
    cudaGetSymbolAddress((void**)&psum, g_psum);
    cudaGetSymbolAddress((void**)&pssq, g_pssq);
    cudaGetSymbolAddress((void**)&sb1, g_sb1);
    cudaGetSymbolAddress((void**)&sb2, g_sb2);

    const int GEMM_SMEM = 2 * 51200;   // 100 KB double-buffered stages
    cudaFuncSetAttribute(gemm_mma<K1_>, cudaFuncAttributeMaxDynamicSharedMemorySize, GEMM_SMEM);
    cudaFuncSetAttribute(gemm_mma<O_>,  cudaFuncAttributeMaxDynamicSharedMemorySize, GEMM_SMEM);

    // prep
    wsplit_kernel<<<(O_ * K1_ + 255) / 256, 256>>>(W0, w0h, w0l, O_ * K1_);
    wsplit_kernel<<<(O_ * O_  + 255) / 256, 256>>>(W1, w1h, w1l, O_ * O_);
    knn_kernel<<<dim3(N_ / 1024, B_), 256>>>(xyz1, xyz2);
    transpose_p2_kernel<<<dim3(S_ / 32, C2_ / 32, B_), dim3(32, 8)>>>(pts2);
    gather_kernel<<<dim3(N_ / 32, B_), 256>>>();
    p1t_kernel<<<dim3(N_ / 32, C1_ / 32, B_), dim3(32, 8)>>>(pts1);

    // layer 1
    gemm_mma<K1_><<<dim3(N_ / 128, B_), 256, GEMM_SMEM>>>(w0h, w0l, xq, b0, y, psum, pssq);
    stats2_kernel<<<256, 256>>>(gg0, be0, sb1);
    splitq_kernel<<<(int)((size_t)B_ * N_ * 64 / 256), 256>>>(y, sb1);

    // layer 2
    gemm_mma<O_><<<dim3(N_ / 128, B_), 256, GEMM_SMEM>>>(w1h, w1l, hq, b1, y, psum, pssq);
    stats2_kernel<<<256, 256>>>(gg1, be1, sb2);

    // output
    outt_kernel<<<dim3(N_ / 32, 8, B_), dim3(32, 8)>>>(y, sb2, out);
}

// round 7
// speedup vs baseline: 2.1712x; 1.1484x over previous
#include <cuda_runtime.h>
#include <cuda_fp16.h>
#include <cstdint>

static constexpr int B_  = 8;
static constexpr int N_  = 16384;
static constexpr int S_  = 2048;
static constexpr int C1_ = 128;
static constexpr int C2_ = 256;
static constexpr int K1_ = 384;
static constexpr int O_  = 256;
static constexpr float BN_EPS  = 1e-5f;
static constexpr float CNT_INV = 1.0f / (float)(B_ * N_);

// ---------------- device-global scratch (no cudaMalloc allowed) ---------------
__device__ __half g_xq[(size_t)B_ * N_ * K1_];   // concat input, fp16 [n][k]
__device__ float  g_y [(size_t)B_ * N_ * O_];    // y1 then y2 (n-major)
__device__ __half g_hq[(size_t)B_ * N_ * O_];    // layer2 input fp16
__device__ float  g_p2t[(size_t)B_ * S_ * C2_];  // points2 transposed [B][S][C]
__device__ int    g_idx[(size_t)B_ * N_ * 3];
__device__ float  g_w  [(size_t)B_ * N_ * 3];
__device__ __half g_w0q[O_ * K1_];               // W0 fp16
__device__ __half g_w1q[O_ * O_];                // W1 fp16
__device__ float  g_psum[256 * 1024], g_pssq[256 * 1024];
__device__ float  g_sb1[512], g_sb2[512];

// ---------------- small PTX helpers ------------------------------------------
__device__ __forceinline__ uint32_t smem_u32(const void* p) {
    uint32_t a;
    asm("{ .reg .u64 t; cvta.to.shared.u64 t, %1; cvt.u32.u64 %0, t; }"
        : "=r"(a) : "l"(p));
    return a;
}
__device__ __forceinline__ void cpa16(uint32_t dst, const void* src) {
    asm volatile("cp.async.cg.shared.global [%0], [%1], 16;"
                 :: "r"(dst), "l"(src) : "memory");
}
#define CP_COMMIT() asm volatile("cp.async.commit_group;" ::: "memory")
#define CP_WAIT0()  asm volatile("cp.async.wait_group 0;" ::: "memory")
#define CP_WAIT1()  asm volatile("cp.async.wait_group 1;" ::: "memory")

__device__ __forceinline__ void ldsm4(uint32_t addr, uint32_t* r) {
    asm volatile("ldmatrix.sync.aligned.m8n8.x4.shared.b16 {%0,%1,%2,%3}, [%4];"
                 : "=r"(r[0]), "=r"(r[1]), "=r"(r[2]), "=r"(r[3]) : "r"(addr));
}
__device__ __forceinline__ void mma16816(float* c, const uint32_t* a, const uint32_t* b) {
    asm volatile(
        "mma.sync.aligned.m16n8k16.row.col.f32.f16.f16.f32 "
        "{%0,%1,%2,%3}, {%4,%5,%6,%7}, {%8,%9}, {%0,%1,%2,%3};"
        : "+f"(c[0]), "+f"(c[1]), "+f"(c[2]), "+f"(c[3])
        : "r"(a[0]), "r"(a[1]), "r"(a[2]), "r"(a[3]), "r"(b[0]), "r"(b[1]));
}

// ---------------- kNN (4 queries per thread) ---------------------------------
__global__ __launch_bounds__(256) void knn_kernel(
    const float* __restrict__ xyz1, const float* __restrict__ xyz2)
{
    __shared__ float4 sp[S_];
    const int b = blockIdx.y;
    const int t = threadIdx.x;
    for (int s = t; s < S_; s += 256) {
        const float* p = xyz2 + ((size_t)b * S_ + s) * 3;
        sp[s] = make_float4(p[0], p[1], p[2], 0.0f);
    }
    __syncthreads();

    const int nb = blockIdx.x * 1024 + t;
    float qx[4], qy[4], qz[4];
    float d0[4], d1[4], d2[4];
    int   i0[4], i1[4], i2[4];
    #pragma unroll
    for (int j = 0; j < 4; j++) {
        const float* q = xyz1 + ((size_t)b * N_ + nb + j * 256) * 3;
        qx[j] = q[0]; qy[j] = q[1]; qz[j] = q[2];
        d0[j] = 3.4e38f; d1[j] = 3.4e38f; d2[j] = 3.4e38f;
        i0[j] = 0; i1[j] = 0; i2[j] = 0;
    }
    #pragma unroll 2
    for (int s = 0; s < S_; s++) {
        float4 p = sp[s];
        #pragma unroll
        for (int j = 0; j < 4; j++) {
            float dx = qx[j] - p.x, dy = qy[j] - p.y, dz = qz[j] - p.z;
            float d = fmaf(dz, dz, fmaf(dy, dy, dx * dx));
            if (d < d2[j]) {
                if (d < d1[j]) {
                    d2[j] = d1[j]; i2[j] = i1[j];
                    if (d < d0[j]) { d1[j] = d0[j]; i1[j] = i0[j]; d0[j] = d; i0[j] = s; }
                    else           { d1[j] = d;  i1[j] = s; }
                } else { d2[j] = d; i2[j] = s; }
            }
        }
    }
    #pragma unroll
    for (int j = 0; j < 4; j++) {
        float a = fmaxf(d0[j], 1e-10f), bb = fmaxf(d1[j], 1e-10f), c = fmaxf(d2[j], 1e-10f);
        float w0 = 1.0f / a, w1 = 1.0f / bb, w2 = 1.0f / c;
        float sw = w0 + w1 + w2;
        size_t base = ((size_t)b * N_ + nb + j * 256) * 3;
        g_idx[base] = i0[j]; g_idx[base + 1] = i1[j]; g_idx[base + 2] = i2[j];
        g_w[base] = w0 / sw; g_w[base + 1] = w1 / sw; g_w[base + 2] = w2 / sw;
    }
}

// ---------------- transpose points2 [B][C][S] -> [B][S][C] --------------------
__global__ void transpose_p2_kernel(const float* __restrict__ p2)
{
    __shared__ float tile[32][33];
    const int b  = blockIdx.z;
    const int s0 = blockIdx.x * 32;
    const int c0 = blockIdx.y * 32;
    #pragma unroll
    for (int r = 0; r < 4; r++) {
        int c = c0 + threadIdx.y + r * 8;
        tile[threadIdx.y + r * 8][threadIdx.x] =
            p2[((size_t)b * C2_ + c) * S_ + s0 + threadIdx.x];
    }
    __syncthreads();
    #pragma unroll
    for (int r = 0; r < 4; r++) {
        int s = s0 + threadIdx.y + r * 8;
        g_p2t[((size_t)b * S_ + s) * C2_ + c0 + threadIdx.x] =
            tile[threadIdx.x][threadIdx.y + r * 8];
    }
}

// ---------------- gather + weighted sum -> xcat channels [0,256) --------------
__global__ __launch_bounds__(256) void gather_kernel()
{
    const int b  = blockIdx.y;
    const int n0 = blockIdx.x * 32;
    const int t  = threadIdx.x;          // channel
    #pragma unroll 2
    for (int nl = 0; nl < 32; nl++) {
        size_t base = ((size_t)b * N_ + n0 + nl) * 3;
        int i0 = g_idx[base], i1 = g_idx[base + 1], i2 = g_idx[base + 2];
        float w0 = g_w[base], w1 = g_w[base + 1], w2 = g_w[base + 2];
        const float* r0 = g_p2t + ((size_t)b * S_ + i0) * C2_;
        const float* r1 = g_p2t + ((size_t)b * S_ + i1) * C2_;
        const float* r2 = g_p2t + ((size_t)b * S_ + i2) * C2_;
        float v = fmaf(w2, r2[t], fmaf(w1, r1[t], w0 * r0[t]));
        g_xq[((size_t)b * N_ + n0 + nl) * K1_ + t] = __float2half_rn(v);
    }
}

// ---------------- points1 transpose -> xcat channels [256,384) ----------------
__global__ void p1t_kernel(const float* __restrict__ p1)
{
    __shared__ float tile[32][33];
    const int b  = blockIdx.z;
    const int n0 = blockIdx.x * 32;
    const int c0 = blockIdx.y * 32;
    #pragma unroll
    for (int r = 0; r < 4; r++) {
        int c = c0 + threadIdx.y + r * 8;
        tile[threadIdx.y + r * 8][threadIdx.x] =
            p1[((size_t)b * C1_ + c) * N_ + n0 + threadIdx.x];
    }
    __syncthreads();
    #pragma unroll
    for (int r = 0; r < 4; r++) {
        int n = n0 + threadIdx.y + r * 8;
        float v = tile[threadIdx.x][threadIdx.y + r * 8];
        g_xq[((size_t)b * N_ + n) * K1_ + 256 + c0 + threadIdx.x] = __float2half_rn(v);
    }
}

// ---------------- weight fp16 convert -----------------------------------------
__global__ void wconv_kernel(const float* __restrict__ w,
                             __half* __restrict__ q, int n)
{
    int i = blockIdx.x * 256 + threadIdx.x;
    if (i < n) q[i] = __float2half_rn(w[i]);
}

// ---------------- mma.sync fp16 GEMM (single-term) ----------------------------
// D[m 0..255][n tile 128] = sum_k W[m][k]*X[n][k]; both single fp16.
// CTA: 256 thr = 8 warps (4 in M x 2 in N). Warp tile 64x64.
// Epilogue: smem-staged coalesced flush to Y (n-major) + BN partials.
template<int KDIM>
__global__ __launch_bounds__(256) void gemm_mma(
    const __half* __restrict__ Aq, const __half* __restrict__ Bq,
    const float* __restrict__ bias, float* __restrict__ Y,
    float* __restrict__ psum, float* __restrict__ pssq)
{
    constexpr int NS = KDIM / 32;                 // K stages of 32
    constexpr uint32_t PITCH  = 80;               // 64B data + 16B pad
    constexpr uint32_t OFF_B  = 256u * PITCH;     // 20480
    constexpr uint32_t STAGE  = OFF_B + 128u * PITCH;  // 30720

    extern __shared__ char sdyn[];
    __shared__ float sm_s[2][256], sm_q[2][256];

    const int tid  = threadIdx.x;
    const int lane = tid & 31, wid = tid >> 5;
    const int mw   = wid & 3;        // M block of 64
    const int nw   = wid >> 2;       // N block of 64
    const int b    = blockIdx.y;
    const int n0   = blockIdx.x * 128;
    const size_t bn0 = (size_t)b * N_ + n0;
    const uint32_t sb0 = smem_u32(sdyn);

    auto load_stage = [&](int kt, int buf) {
        uint32_t base = sb0 + (uint32_t)buf * STAGE;
        #pragma unroll
        for (int i = 0; i < 4; i++) {              // A: 256 rows x 4 chunks
            int c = tid + i * 256;
            int row = (c >> 2) & 255, ch = c & 3;
            const __half* src = Aq + (size_t)row * KDIM + kt + ch * 8;
            cpa16(base + (uint32_t)row * PITCH + ch * 16, src);
        }
        #pragma unroll
        for (int i = 0; i < 2; i++) {              // B: 128 rows x 4 chunks
            int c = tid + i * 256;
            int row = (c >> 2) & 127, ch = c & 3;
            const __half* src = Bq + (bn0 + row) * KDIM + kt + ch * 8;
            cpa16(base + OFF_B + (uint32_t)row * PITCH + ch * 16, src);
        }
        CP_COMMIT();
    };

    float acc[4][8][4] = {};

    load_stage(0, 0);

    #pragma unroll 1
    for (int s = 0; s < NS; s++) {
        if (s + 1 < NS) { load_stage((s + 1) * 32, (s + 1) & 1); CP_WAIT1(); }
        else            { CP_WAIT0(); }
        __syncthreads();

        uint32_t base = sb0 + (uint32_t)(s & 1) * STAGE;
        #pragma unroll
        for (int ks = 0; ks < 2; ks++) {
            uint32_t a[4][4];
            #pragma unroll
            for (int mt = 0; mt < 4; mt++) {
                uint32_t row = (uint32_t)(mw * 64 + mt * 16 + (lane & 15));
                ldsm4(base + row * PITCH + ks * 32 + ((lane >> 4) << 4), a[mt]);
            }
            #pragma unroll
            for (int ntp = 0; ntp < 4; ntp++) {
                uint32_t rowB = (uint32_t)(nw * 64 + ntp * 16
                               + ((lane >> 4) << 3) + (lane & 7));
                uint32_t bfr[4];
                ldsm4(base + OFF_B + rowB * PITCH
                      + ks * 32 + (((lane >> 3) & 1) << 4), bfr);
                #pragma unroll
                for (int h = 0; h < 2; h++) {
                    int nt = ntp * 2 + h;
                    #pragma unroll
                    for (int mt = 0; mt < 4; mt++)
                        mma16816(acc[mt][nt], a[mt], &bfr[h * 2]);
                }
            }
        }
        __syncthreads();
    }

    // ---- epilogue: bias, BN partials, smem-staged coalesced flush ------------
    float* sy = (float*)sdyn;             // [64][260] per N-half
    const int r = lane >> 2;
    float csum[8] = {}, cssq[8] = {};

    #pragma unroll
    for (int half = 0; half < 2; half++) {
        if (nw == half) {
            #pragma unroll
            for (int mt = 0; mt < 4; mt++) {
                const int m0 = mw * 64 + mt * 16 + r;
                const int m1 = m0 + 8;
                const float bv0 = bias[m0], bv1 = bias[m1];
                #pragma unroll
                for (int nt = 0; nt < 8; nt++) {
                    float* c = acc[mt][nt];
                    int nl = nt * 8 + (lane & 3) * 2;
                    float v0 = c[0] + bv0, v1 = c[1] + bv0;
                    float v2 = c[2] + bv1, v3 = c[3] + bv1;
                    sy[nl * 260 + m0]       = v0;
                    sy[(nl + 1) * 260 + m0] = v1;
                    sy[nl * 260 + m1]       = v2;
                    sy[(nl + 1) * 260 + m1] = v3;
                    csum[mt * 2]     += v0 + v1;
                    cssq[mt * 2]     += fmaf(v0, v0, v1 * v1);
                    csum[mt * 2 + 1] += v2 + v3;
                    cssq[mt * 2 + 1] += fmaf(v2, v2, v3 * v3);
                }
            }
        }
        __syncthreads();
        // coalesced flush: 64 rows x 1KB
        #pragma unroll 8
        for (int row = 0; row < 64; row++)
            Y[(bn0 + half * 64 + row) * 256 + tid] = sy[row * 260 + tid];
        __syncthreads();
    }

    // BN partials
    #pragma unroll
    for (int j = 0; j < 8; j++) {
        csum[j] += __shfl_xor_sync(0xffffffffu, csum[j], 1);
        csum[j] += __shfl_xor_sync(0xffffffffu, csum[j], 2);
        cssq[j] += __shfl_xor_sync(0xffffffffu, cssq[j], 1);
        cssq[j] += __shfl_xor_sync(0xffffffffu, cssq[j], 2);
    }
    if ((lane & 3) == 0) {
        #pragma unroll
        for (int mt = 0; mt < 4; mt++) {
            #pragma unroll
            for (int h = 0; h < 2; h++) {
                int ch = mw * 64 + mt * 16 + r + h * 8;
                sm_s[nw][ch] = csum[mt * 2 + h];
                sm_q[nw][ch] = cssq[mt * 2 + h];
            }
        }
    }
    __syncthreads();
    {
        int cta = blockIdx.x + blockIdx.y * gridDim.x;
        psum[tid * 1024 + cta] = sm_s[0][tid] + sm_s[1][tid];
        pssq[tid * 1024 + cta] = sm_q[0][tid] + sm_q[1][tid];
    }
}

// ---------------- BN fold: reduce 1024 partials per channel -------------------
__global__ __launch_bounds__(256) void stats2_kernel(
    const float* __restrict__ g, const float* __restrict__ beta,
    float* __restrict__ sb)
{
    const int o = blockIdx.x;
    const int t = threadIdx.x;
    float s = 0.0f, ss = 0.0f;
    #pragma unroll
    for (int i = 0; i < 4; i++) {
        s  += g_psum[o * 1024 + t * 4 + i];
        ss += g_pssq[o * 1024 + t * 4 + i];
    }
    const int lane = t & 31, w = t >> 5;
    #pragma unroll
    for (int off = 16; off; off >>= 1) {
        s  += __shfl_down_sync(0xffffffffu, s,  off);
        ss += __shfl_down_sync(0xffffffffu, ss, off);
    }
    __shared__ float rs[8], rss[8];
    if (lane == 0) { rs[w] = s; rss[w] = ss; }
    __syncthreads();
    if (t == 0) {
        float ts = 0.0f, tss = 0.0f;
        #pragma unroll
        for (int i = 0; i < 8; i++) { ts += rs[i]; tss += rss[i]; }
        float mean = ts * CNT_INV;
        float var  = tss * CNT_INV - mean * mean;
        float rstd = rsqrtf(var + BN_EPS);
        float sc = g[o] * rstd;
        sb[o]       = sc;
        sb[256 + o] = beta[o] - mean * sc;
    }
}

// ---------------- layer-1 norm + relu + fp16 quantize -> h --------------------
__global__ __launch_bounds__(256) void splitq_kernel(
    const float* __restrict__ y, const float* __restrict__ sb)
{
    size_t i4 = (size_t)blockIdx.x * 256 + threadIdx.x;   // over B*N*64
    int c4 = (int)(i4 & 63) * 4;
    float4 v  = ((const float4*)y)[i4];
    float4 sc = *(const float4*)(sb + c4);
    float4 bs = *(const float4*)(sb + 256 + c4);
    float a0 = fmaxf(fmaf(v.x, sc.x, bs.x), 0.0f);
    float a1 = fmaxf(fmaf(v.y, sc.y, bs.y), 0.0f);
    float a2 = fmaxf(fmaf(v.z, sc.z, bs.z), 0.0f);
    float a3 = fmaxf(fmaf(v.w, sc.w, bs.w), 0.0f);
    uint2 p;
    __half h0 = __float2half_rn(a0), h1 = __float2half_rn(a1);
    __half h2 = __float2half_rn(a2), h3 = __float2half_rn(a3);
    p.x = (uint32_t)__half_as_ushort(h0) | ((uint32_t)__half_as_ushort(h1) << 16);
    p.y = (uint32_t)__half_as_ushort(h2) | ((uint32_t)__half_as_ushort(h3) << 16);
    ((uint2*)g_hq)[i4] = p;
}

// ---------------- final norm + relu + transpose -> out [B][256][N] ------------
__global__ __launch_bounds__(256) void outt_kernel(
    const float* __restrict__ y, const float* __restrict__ sb,
    float* __restrict__ out)
{
    __shared__ float tile[32][33];
    const int b  = blockIdx.z;
    const int n0 = blockIdx.x * 32;
    const int m0 = blockIdx.y * 32;
    const float sc = sb[m0 + threadIdx.x];
    const float bs = sb[256 + m0 + threadIdx.x];
    #pragma unroll
    for (int r = 0; r < 4; r++) {
        int n = n0 + threadIdx.y + r * 8;
        float v = y[((size_t)b * N_ + n) * 256 + m0 + threadIdx.x];
        tile[threadIdx.y + r * 8][threadIdx.x] = fmaxf(fmaf(v, sc, bs), 0.0f);
    }
    __syncthreads();
    #pragma unroll
    for (int r = 0; r < 4; r++) {
        int m = m0 + threadIdx.y + r * 8;
        out[((size_t)b * 256 + m) * N_ + n0 + threadIdx.x] =
            tile[threadIdx.x][threadIdx.y + r * 8];
    }
}

// ---------------- launcher ----------------------------------------------------
extern "C" void kernel_launch(void* const* d_in, const int* in_sizes, int n_in,
                              void* d_out, int out_size)
{
    const float* xyz1 = (const float*)d_in[0];
    const float* xyz2 = (const float*)d_in[1];
    const float* pts1 = (const float*)d_in[2];
    const float* pts2 = (const float*)d_in[3];
    const float* W0   = (const float*)d_in[4];
    const float* b0   = (const float*)d_in[5];
    const float* gg0  = (const float*)d_in[6];
    const float* be0  = (const float*)d_in[7];
    const float* W1   = (const float*)d_in[8];
    const float* b1   = (const float*)d_in[9];
    const float* gg1  = (const float*)d_in[10];
    const float* be1  = (const float*)d_in[11];
    float* out = (float*)d_out;

    __half *xq, *hq, *w0q, *w1q;
    float *y, *psum, *pssq, *sb1, *sb2;
    cudaGetSymbolAddress((void**)&xq,  g_xq);
    cudaGetSymbolAddress((void**)&hq,  g_hq);
    cudaGetSymbolAddress((void**)&w0q, g_w0q);
    cudaGetSymbolAddress((void**)&w1q, g_w1q);
    cudaGetSymbolAddress((void**)&y,   g_y);
    cudaGetSymbolAddress((void**)&psum, g_psum);
    cudaGetSymbolAddress((void**)&pssq, g_pssq);
    cudaGetSymbolAddress((void**)&sb1, g_sb1);
    cudaGetSymbolAddress((void**)&sb2, g_sb2);

    const int GEMM_SMEM = 68096;   // max(2 stages 61440, sy 64*260*4=66560) +pad
    cudaFuncSetAttribute(gemm_mma<K1_>, cudaFuncAttributeMaxDynamicSharedMemorySize, GEMM_SMEM);
    cudaFuncSetAttribute(gemm_mma<O_>,  cudaFuncAttributeMaxDynamicSharedMemorySize, GEMM_SMEM);

    // prep
    wconv_kernel<<<(O_ * K1_ + 255) / 256, 256>>>(W0, w0q, O_ * K1_);
    wconv_kernel<<<(O_ * O_  + 255) / 256, 256>>>(W1, w1q, O_ * O_);
    knn_kernel<<<dim3(N_ / 1024, B_), 256>>>(xyz1, xyz2);
    transpose_p2_kernel<<<dim3(S_ / 32, C2_ / 32, B_), dim3(32, 8)>>>(pts2);
    gather_kernel<<<dim3(N_ / 32, B_), 256>>>();
    p1t_kernel<<<dim3(N_ / 32, C1_ / 32, B_), dim3(32, 8)>>>(pts1);

    // layer 1
    gemm_mma<K1_><<<dim3(N_ / 128, B_), 256, GEMM_SMEM>>>(w0q, xq, b0, y, psum, pssq);
    stats2_kernel<<<256, 256>>>(gg0, be0, sb1);
    splitq_kernel<<<(int)((size_t)B_ * N_ * 64 / 256), 256>>>(y, sb1);

    // layer 2
    gemm_mma<O_><<<dim3(N_ / 128, B_), 256, GEMM_SMEM>>>(w1q, hq, b1, y, psum, pssq);
    stats2_kernel<<<256, 256>>>(gg1, be1, sb2);

    // output
    outt_kernel<<<dim3(N_ / 32, 8, B_), dim3(32, 8)>>>(y, sb2, out);
}

// round 8
// speedup vs baseline: 2.2863x; 1.0530x over previous
#include <cuda_runtime.h>
#include <cuda_fp16.h>
#include <cstdint>

static constexpr int B_  = 8;
static constexpr int N_  = 16384;
static constexpr int S_  = 2048;
static constexpr int C1_ = 128;
static constexpr int C2_ = 256;
static constexpr int K1_ = 384;
static constexpr int O_  = 256;
static constexpr float BN_EPS  = 1e-5f;
static constexpr float CNT_INV = 1.0f / (float)(B_ * N_);

// ---------------- device-global scratch (no cudaMalloc allowed) ---------------
__device__ __half g_xq[(size_t)B_ * N_ * K1_];   // concat input, fp16 [n][k]
__device__ __half g_y [(size_t)B_ * N_ * O_];    // y1 then y2, fp16 (n-major)
__device__ __half g_hq[(size_t)B_ * N_ * O_];    // layer2 input fp16
__device__ float  g_p2t[(size_t)B_ * S_ * C2_];  // points2 transposed [B][S][C]
__device__ int    g_idx[(size_t)B_ * N_ * 3];
__device__ float  g_w  [(size_t)B_ * N_ * 3];
__device__ __half g_w0q[O_ * K1_];               // W0 fp16
__device__ __half g_w1q[O_ * O_];                // W1 fp16
__device__ float  g_psum[256 * 1024], g_pssq[256 * 1024];
__device__ float  g_sb1[512], g_sb2[512];

// ---------------- small PTX helpers ------------------------------------------
__device__ __forceinline__ uint32_t smem_u32(const void* p) {
    uint32_t a;
    asm("{ .reg .u64 t; cvta.to.shared.u64 t, %1; cvt.u32.u64 %0, t; }"
        : "=r"(a) : "l"(p));
    return a;
}
__device__ __forceinline__ void cpa16(uint32_t dst, const void* src) {
    asm volatile("cp.async.cg.shared.global [%0], [%1], 16;"
                 :: "r"(dst), "l"(src) : "memory");
}
#define CP_COMMIT() asm volatile("cp.async.commit_group;" ::: "memory")
#define CP_WAIT0()  asm volatile("cp.async.wait_group 0;" ::: "memory")
#define CP_WAIT1()  asm volatile("cp.async.wait_group 1;" ::: "memory")

__device__ __forceinline__ void ldsm4(uint32_t addr, uint32_t* r) {
    asm volatile("ldmatrix.sync.aligned.m8n8.x4.shared.b16 {%0,%1,%2,%3}, [%4];"
                 : "=r"(r[0]), "=r"(r[1]), "=r"(r[2]), "=r"(r[3]) : "r"(addr));
}
__device__ __forceinline__ void mma16816(float* c, const uint32_t* a, const uint32_t* b) {
    asm volatile(
        "mma.sync.aligned.m16n8k16.row.col.f32.f16.f16.f32 "
        "{%0,%1,%2,%3}, {%4,%5,%6,%7}, {%8,%9}, {%0,%1,%2,%3};"
        : "+f"(c[0]), "+f"(c[1]), "+f"(c[2]), "+f"(c[3])
        : "r"(a[0]), "r"(a[1]), "r"(a[2]), "r"(a[3]), "r"(b[0]), "r"(b[1]));
}

// ---------------- kNN (4 queries per thread) ---------------------------------
__global__ __launch_bounds__(256) void knn_kernel(
    const float* __restrict__ xyz1, const float* __restrict__ xyz2)
{
    __shared__ float4 sp[S_];
    const int b = blockIdx.y;
    const int t = threadIdx.x;
    for (int s = t; s < S_; s += 256) {
        const float* p = xyz2 + ((size_t)b * S_ + s) * 3;
        sp[s] = make_float4(p[0], p[1], p[2], 0.0f);
    }
    __syncthreads();

    const int nb = blockIdx.x * 1024 + t;
    float qx[4], qy[4], qz[4];
    float d0[4], d1[4], d2[4];
    int   i0[4], i1[4], i2[4];
    #pragma unroll
    for (int j = 0; j < 4; j++) {
        const float* q = xyz1 + ((size_t)b * N_ + nb + j * 256) * 3;
        qx[j] = q[0]; qy[j] = q[1]; qz[j] = q[2];
        d0[j] = 3.4e38f; d1[j] = 3.4e38f; d2[j] = 3.4e38f;
        i0[j] = 0; i1[j] = 0; i2[j] = 0;
    }
    #pragma unroll 2
    for (int s = 0; s < S_; s++) {
        float4 p = sp[s];
        #pragma unroll
        for (int j = 0; j < 4; j++) {
            float dx = qx[j] - p.x, dy = qy[j] - p.y, dz = qz[j] - p.z;
            float d = fmaf(dz, dz, fmaf(dy, dy, dx * dx));
            if (d < d2[j]) {
                if (d < d1[j]) {
                    d2[j] = d1[j]; i2[j] = i1[j];
                    if (d < d0[j]) { d1[j] = d0[j]; i1[j] = i0[j]; d0[j] = d; i0[j] = s; }
                    else           { d1[j] = d;  i1[j] = s; }
                } else { d2[j] = d; i2[j] = s; }
            }
        }
    }
    #pragma unroll
    for (int j = 0; j < 4; j++) {
        float a = fmaxf(d0[j], 1e-10f), bb = fmaxf(d1[j], 1e-10f), c = fmaxf(d2[j], 1e-10f);
        float w0 = 1.0f / a, w1 = 1.0f / bb, w2 = 1.0f / c;
        float sw = w0 + w1 + w2;
        size_t base = ((size_t)b * N_ + nb + j * 256) * 3;
        g_idx[base] = i0[j]; g_idx[base + 1] = i1[j]; g_idx[base + 2] = i2[j];
        g_w[base] = w0 / sw; g_w[base + 1] = w1 / sw; g_w[base + 2] = w2 / sw;
    }
}

// ---------------- transpose points2 [B][C][S] -> [B][S][C] --------------------
__global__ void transpose_p2_kernel(const float* __restrict__ p2)
{
    __shared__ float tile[32][33];
    const int b  = blockIdx.z;
    const int s0 = blockIdx.x * 32;
    const int c0 = blockIdx.y * 32;
    #pragma unroll
    for (int r = 0; r < 4; r++) {
        int c = c0 + threadIdx.y + r * 8;
        tile[threadIdx.y + r * 8][threadIdx.x] =
            p2[((size_t)b * C2_ + c) * S_ + s0 + threadIdx.x];
    }
    __syncthreads();
    #pragma unroll
    for (int r = 0; r < 4; r++) {
        int s = s0 + threadIdx.y + r * 8;
        g_p2t[((size_t)b * S_ + s) * C2_ + c0 + threadIdx.x] =
            tile[threadIdx.x][threadIdx.y + r * 8];
    }
}

// ---------------- gather + weighted sum -> xcat channels [0,256) --------------
__global__ __launch_bounds__(256) void gather_kernel()
{
    const int b  = blockIdx.y;
    const int n0 = blockIdx.x * 32;
    const int t  = threadIdx.x;          // channel
    #pragma unroll 2
    for (int nl = 0; nl < 32; nl++) {
        size_t base = ((size_t)b * N_ + n0 + nl) * 3;
        int i0 = g_idx[base], i1 = g_idx[base + 1], i2 = g_idx[base + 2];
        float w0 = g_w[base], w1 = g_w[base + 1], w2 = g_w[base + 2];
        const float* r0 = g_p2t + ((size_t)b * S_ + i0) * C2_;
        const float* r1 = g_p2t + ((size_t)b * S_ + i1) * C2_;
        const float* r2 = g_p2t + ((size_t)b * S_ + i2) * C2_;
        float v = fmaf(w2, r2[t], fmaf(w1, r1[t], w0 * r0[t]));
        g_xq[((size_t)b * N_ + n0 + nl) * K1_ + t] = __float2half_rn(v);
    }
}

// ---------------- points1 transpose -> xcat channels [256,384) ----------------
__global__ void p1t_kernel(const float* __restrict__ p1)
{
    __shared__ float tile[32][33];
    const int b  = blockIdx.z;
    const int n0 = blockIdx.x * 32;
    const int c0 = blockIdx.y * 32;
    #pragma unroll
    for (int r = 0; r < 4; r++) {
        int c = c0 + threadIdx.y + r * 8;
        tile[threadIdx.y + r * 8][threadIdx.x] =
            p1[((size_t)b * C1_ + c) * N_ + n0 + threadIdx.x];
    }
    __syncthreads();
    #pragma unroll
    for (int r = 0; r < 4; r++) {
        int n = n0 + threadIdx.y + r * 8;
        float v = tile[threadIdx.x][threadIdx.y + r * 8];
        g_xq[((size_t)b * N_ + n) * K1_ + 256 + c0 + threadIdx.x] = __float2half_rn(v);
    }
}

// ---------------- weight fp16 convert -----------------------------------------
__global__ void wconv_kernel(const float* __restrict__ w,
                             __half* __restrict__ q, int n)
{
    int i = blockIdx.x * 256 + threadIdx.x;
    if (i < n) q[i] = __float2half_rn(w[i]);
}

// ---------------- mma.sync fp16 GEMM (single-term, fp16 y output) -------------
// D[m 0..255][n tile 128] = sum_k W[m][k]*X[n][k]; both single fp16.
// CTA: 256 thr = 8 warps (4 in M x 2 in N). Warp tile 64x64.
// Epilogue: BN partials from fp32 accs; y stored fp16 via smem-staged flush.
template<int KDIM>
__global__ __launch_bounds__(256) void gemm_mma(
    const __half* __restrict__ Aq, const __half* __restrict__ Bq,
    const float* __restrict__ bias, __half* __restrict__ Y,
    float* __restrict__ psum, float* __restrict__ pssq)
{
    constexpr int NS = KDIM / 32;                 // K stages of 32
    constexpr uint32_t PITCH  = 80;               // 64B data + 16B pad
    constexpr uint32_t OFF_B  = 256u * PITCH;     // 20480
    constexpr uint32_t STAGE  = OFF_B + 128u * PITCH;  // 30720

    extern __shared__ char sdyn[];
    __shared__ float sm_s[2][256], sm_q[2][256];

    const int tid  = threadIdx.x;
    const int lane = tid & 31, wid = tid >> 5;
    const int mw   = wid & 3;        // M block of 64
    const int nw   = wid >> 2;       // N block of 64
    const int b    = blockIdx.y;
    const int n0   = blockIdx.x * 128;
    const size_t bn0 = (size_t)b * N_ + n0;
    const uint32_t sb0 = smem_u32(sdyn);

    auto load_stage = [&](int kt, int buf) {
        uint32_t base = sb0 + (uint32_t)buf * STAGE;
        #pragma unroll
        for (int i = 0; i < 4; i++) {              // A: 256 rows x 4 chunks
            int c = tid + i * 256;
            int row = (c >> 2) & 255, ch = c & 3;
            const __half* src = Aq + (size_t)row * KDIM + kt + ch * 8;
            cpa16(base + (uint32_t)row * PITCH + ch * 16, src);
        }
        #pragma unroll
        for (int i = 0; i < 2; i++) {              // B: 128 rows x 4 chunks
            int c = tid + i * 256;
            int row = (c >> 2) & 127, ch = c & 3;
            const __half* src = Bq + (bn0 + row) * KDIM + kt + ch * 8;
            cpa16(base + OFF_B + (uint32_t)row * PITCH + ch * 16, src);
        }
        CP_COMMIT();
    };

    float acc[4][8][4] = {};

    load_stage(0, 0);

    #pragma unroll 1
    for (int s = 0; s < NS; s++) {
        if (s + 1 < NS) { load_stage((s + 1) * 32, (s + 1) & 1); CP_WAIT1(); }
        else            { CP_WAIT0(); }
        __syncthreads();

        uint32_t base = sb0 + (uint32_t)(s & 1) * STAGE;
        #pragma unroll
        for (int ks = 0; ks < 2; ks++) {
            uint32_t a[4][4];
            #pragma unroll
            for (int mt = 0; mt < 4; mt++) {
                uint32_t row = (uint32_t)(mw * 64 + mt * 16 + (lane & 15));
                ldsm4(base + row * PITCH + ks * 32 + ((lane >> 4) << 4), a[mt]);
            }
            #pragma unroll
            for (int ntp = 0; ntp < 4; ntp++) {
                uint32_t rowB = (uint32_t)(nw * 64 + ntp * 16
                               + ((lane >> 4) << 3) + (lane & 7));
                uint32_t bfr[4];
                ldsm4(base + OFF_B + rowB * PITCH
                      + ks * 32 + (((lane >> 3) & 1) << 4), bfr);
                #pragma unroll
                for (int h = 0; h < 2; h++) {
                    int nt = ntp * 2 + h;
                    #pragma unroll
                    for (int mt = 0; mt < 4; mt++)
                        mma16816(acc[mt][nt], a[mt], &bfr[h * 2]);
                }
            }
        }
        __syncthreads();
    }

    // ---- epilogue: bias, BN partials, smem-staged fp16 coalesced flush -------
    float* sy = (float*)sdyn;             // [64][260] per N-half
    const int r = lane >> 2;
    float csum[8] = {}, cssq[8] = {};

    #pragma unroll
    for (int half = 0; half < 2; half++) {
        if (nw == half) {
            #pragma unroll
            for (int mt = 0; mt < 4; mt++) {
                const int m0 = mw * 64 + mt * 16 + r;
                const int m1 = m0 + 8;
                const float bv0 = bias[m0], bv1 = bias[m1];
                #pragma unroll
                for (int nt = 0; nt < 8; nt++) {
                    float* c = acc[mt][nt];
                    int nl = nt * 8 + (lane & 3) * 2;
                    float v0 = c[0] + bv0, v1 = c[1] + bv0;
                    float v2 = c[2] + bv1, v3 = c[3] + bv1;
                    sy[nl * 260 + m0]       = v0;
                    sy[(nl + 1) * 260 + m0] = v1;
                    sy[nl * 260 + m1]       = v2;
                    sy[(nl + 1) * 260 + m1] = v3;
                    csum[mt * 2]     += v0 + v1;
                    cssq[mt * 2]     += fmaf(v0, v0, v1 * v1);
                    csum[mt * 2 + 1] += v2 + v3;
                    cssq[mt * 2 + 1] += fmaf(v2, v2, v3 * v3);
                }
            }
        }
        __syncthreads();
        // coalesced fp16 flush: 64 rows x 512B, two rows per iteration
        #pragma unroll 8
        for (int i = 0; i < 32; i++) {
            int row = i * 2 + (tid >> 7);
            int c2  = tid & 127;
            __half2 hp = __floats2half2_rn(sy[row * 260 + c2 * 2],
                                           sy[row * 260 + c2 * 2 + 1]);
            *(__half2*)(Y + (bn0 + half * 64 + row) * 256 + c2 * 2) = hp;
        }
        __syncthreads();
    }

    // BN partials
    #pragma unroll
    for (int j = 0; j < 8; j++) {
        csum[j] += __shfl_xor_sync(0xffffffffu, csum[j], 1);
        csum[j] += __shfl_xor_sync(0xffffffffu, csum[j], 2);
        cssq[j] += __shfl_xor_sync(0xffffffffu, cssq[j], 1);
        cssq[j] += __shfl_xor_sync(0xffffffffu, cssq[j], 2);
    }
    if ((lane & 3) == 0) {
        #pragma unroll
        for (int mt = 0; mt < 4; mt++) {
            #pragma unroll
            for (int h = 0; h < 2; h++) {
                int ch = mw * 64 + mt * 16 + r + h * 8;
                sm_s[nw][ch] = csum[mt * 2 + h];
                sm_q[nw][ch] = cssq[mt * 2 + h];
            }
        }
    }
    __syncthreads();
    {
        int cta = blockIdx.x + blockIdx.y * gridDim.x;
        psum[tid * 1024 + cta] = sm_s[0][tid] + sm_s[1][tid];
        pssq[tid * 1024 + cta] = sm_q[0][tid] + sm_q[1][tid];
    }
}

// ---------------- BN fold: reduce 1024 partials per channel -------------------
__global__ __launch_bounds__(256) void stats2_kernel(
    const float* __restrict__ g, const float* __restrict__ beta,
    float* __restrict__ sb)
{
    const int o = blockIdx.x;
    const int t = threadIdx.x;
    float s = 0.0f, ss = 0.0f;
    #pragma unroll
    for (int i = 0; i < 4; i++) {
        s  += g_psum[o * 1024 + t * 4 + i];
        ss += g_pssq[o * 1024 + t * 4 + i];
    }
    const int lane = t & 31, w = t >> 5;
    #pragma unroll
    for (int off = 16; off; off >>= 1) {
        s  += __shfl_down_sync(0xffffffffu, s,  off);
        ss += __shfl_down_sync(0xffffffffu, ss, off);
    }
    __shared__ float rs[8], rss[8];
    if (lane == 0) { rs[w] = s; rss[w] = ss; }
    __syncthreads();
    if (t == 0) {
        float ts = 0.0f, tss = 0.0f;
        #pragma unroll
        for (int i = 0; i < 8; i++) { ts += rs[i]; tss += rss[i]; }
        float mean = ts * CNT_INV;
        float var  = tss * CNT_INV - mean * mean;
        float rstd = rsqrtf(var + BN_EPS);
        float sc = g[o] * rstd;
        sb[o]       = sc;
        sb[256 + o] = beta[o] - mean * sc;
    }
}

// ---------------- layer-1 norm + relu -> hq (fp16 in, fp16 out) ---------------
__global__ __launch_bounds__(256) void splitq_kernel(
    const __half* __restrict__ y, const float* __restrict__ sb)
{
    size_t i4 = (size_t)blockIdx.x * 256 + threadIdx.x;   // over B*N*64
    int c4 = (int)(i4 & 63) * 4;
    uint2 raw = ((const uint2*)y)[i4];
    __half2 p0 = *(__half2*)&raw.x, p1 = *(__half2*)&raw.y;
    float2 f0 = __half22float2(p0), f1 = __half22float2(p1);
    float4 sc = *(const float4*)(sb + c4);
    float4 bs = *(const float4*)(sb + 256 + c4);
    float a0 = fmaxf(fmaf(f0.x, sc.x, bs.x), 0.0f);
    float a1 = fmaxf(fmaf(f0.y, sc.y, bs.y), 0.0f);
    float a2 = fmaxf(fmaf(f1.x, sc.z, bs.z), 0.0f);
    float a3 = fmaxf(fmaf(f1.y, sc.w, bs.w), 0.0f);
    uint2 p;
    __half2 h0 = __floats2half2_rn(a0, a1);
    __half2 h1 = __floats2half2_rn(a2, a3);
    p.x = *(uint32_t*)&h0;
    p.y = *(uint32_t*)&h1;
    ((uint2*)g_hq)[i4] = p;
}

// ---------------- final norm + relu + transpose -> out [B][256][N] ------------
__global__ __launch_bounds__(256) void outt_kernel(
    const __half* __restrict__ y, const float* __restrict__ sb,
    float* __restrict__ out)
{
    __shared__ float tile[32][33];
    const int b  = blockIdx.z;
    const int n0 = blockIdx.x * 32;
    const int m0 = blockIdx.y * 32;
    const float sc = sb[m0 + threadIdx.x];
    const float bs = sb[256 + m0 + threadIdx.x];
    #pragma unroll
    for (int r = 0; r < 4; r++) {
        int n = n0 + threadIdx.y + r * 8;
        float v = __half2float(y[((size_t)b * N_ + n) * 256 + m0 + threadIdx.x]);
        tile[threadIdx.y + r * 8][threadIdx.x] = fmaxf(fmaf(v, sc, bs), 0.0f);
    }
    __syncthreads();
    #pragma unroll
    for (int r = 0; r < 4; r++) {
        int m = m0 + threadIdx.y + r * 8;
        out[((size_t)b * 256 + m) * N_ + n0 + threadIdx.x] =
            tile[threadIdx.x][threadIdx.y + r * 8];
    }
}

// ---------------- launcher ----------------------------------------------------
extern "C" void kernel_launch(void* const* d_in, const int* in_sizes, int n_in,
                              void* d_out, int out_size)
{
    const float* xyz1 = (const float*)d_in[0];
    const float* xyz2 = (const float*)d_in[1];
    const float* pts1 = (const float*)d_in[2];
    const float* pts2 = (const float*)d_in[3];
    const float* W0   = (const float*)d_in[4];
    const float* b0   = (const float*)d_in[5];
    const float* gg0  = (const float*)d_in[6];
    const float* be0  = (const float*)d_in[7];
    const float* W1   = (const float*)d_in[8];
    const float* b1   = (const float*)d_in[9];
    const float* gg1  = (const float*)d_in[10];
    const float* be1  = (const float*)d_in[11];
    float* out = (float*)d_out;

    __half *xq, *hq, *w0q, *w1q, *y;
    float *psum, *pssq, *sb1, *sb2;
    cudaGetSymbolAddress((void**)&xq,  g_xq);
    cudaGetSymbolAddress((void**)&hq,  g_hq);
    cudaGetSymbolAddress((void**)&w0q, g_w0q);
    cudaGetSymbolAddress((void**)&w1q, g_w1q);
    cudaGetSymbolAddress((void**)&y,   g_y);
    cudaGetSymbolAddress((void**)&psum, g_psum);
    cudaGetSymbolAddress((void**)&pssq, g_pssq);
    cudaGetSymbolAddress((void**)&sb1, g_sb1);
    cudaGetSymbolAddress((void**)&sb2, g_sb2);

    const int GEMM_SMEM = 68096;   // max(2 stages 61440, sy 64*260*4=66560) +pad
    cudaFuncSetAttribute(gemm_mma<K1_>, cudaFuncAttributeMaxDynamicSharedMemorySize, GEMM_SMEM);
    cudaFuncSetAttribute(gemm_mma<O_>,  cudaFuncAttributeMaxDynamicSharedMemorySize, GEMM_SMEM);

    // prep
    wconv_kernel<<<(O_ * K1_ + 255) / 256, 256>>>(W0, w0q, O_ * K1_);
    wconv_kernel<<<(O_ * O_  + 255) / 256, 256>>>(W1, w1q, O_ * O_);
    knn_kernel<<<dim3(N_ / 1024, B_), 256>>>(xyz1, xyz2);
    transpose_p2_kernel<<<dim3(S_ / 32, C2_ / 32, B_), dim3(32, 8)>>>(pts2);
    gather_kernel<<<dim3(N_ / 32, B_), 256>>>();
    p1t_kernel<<<dim3(N_ / 32, C1_ / 32, B_), dim3(32, 8)>>>(pts1);

    // layer 1
    gemm_mma<K1_><<<dim3(N_ / 128, B_), 256, GEMM_SMEM>>>(w0q, xq, b0, y, psum, pssq);
    stats2_kernel<<<256, 256>>>(gg0, be0, sb1);
    splitq_kernel<<<(int)((size_t)B_ * N_ * 64 / 256), 256>>>(y, sb1);

    // layer 2
    gemm_mma<O_><<<dim3(N_ / 128, B_), 256, GEMM_SMEM>>>(w1q, hq, b1, y, psum, pssq);
    stats2_kernel<<<256, 256>>>(gg1, be1, sb2);

    // output
    outt_kernel<<<dim3(N_ / 32, 8, B_), dim3(32, 8)>>>(y, sb2, out);
}

// round 10
// speedup vs baseline: 2.3283x; 1.0184x over previous
#include <cuda_runtime.h>
#include <cuda_fp16.h>
#include <cstdint>

static constexpr int B_  = 8;
static constexpr int N_  = 16384;
static constexpr int S_  = 2048;
static constexpr int C1_ = 128;
static constexpr int C2_ = 256;
static constexpr int K1_ = 384;
static constexpr int O_  = 256;
static constexpr float BN_EPS  = 1e-5f;
static constexpr float CNT_INV = 1.0f / (float)(B_ * N_);

// ---------------- device-global scratch (no cudaMalloc allowed) ---------------
__device__ __half g_xq[(size_t)B_ * N_ * K1_];   // concat input, fp16 [n][k]
__device__ __half g_y [(size_t)B_ * N_ * O_];    // y1 then y2, fp16 (n-major)
__device__ float  g_p2t[(size_t)B_ * S_ * C2_];  // points2 transposed [B][S][C]
__device__ int    g_idx[(size_t)B_ * N_ * 3];
__device__ float  g_w  [(size_t)B_ * N_ * 3];
__device__ __half g_w0q[O_ * K1_];               // W0 fp16
__device__ __half g_w1q[O_ * O_];                // W1 fp16
__device__ float  g_psum[256 * 1024], g_pssq[256 * 1024];
__device__ float  g_sb1[512], g_sb2[512];

// ---------------- small PTX helpers ------------------------------------------
__device__ __forceinline__ uint32_t smem_u32(const void* p) {
    uint32_t a;
    asm("{ .reg .u64 t; cvta.to.shared.u64 t, %1; cvt.u32.u64 %0, t; }"
        : "=r"(a) : "l"(p));
    return a;
}
__device__ __forceinline__ void cpa16(uint32_t dst, const void* src) {
    asm volatile("cp.async.cg.shared.global [%0], [%1], 16;"
                 :: "r"(dst), "l"(src) : "memory");
}
#define CP_COMMIT() asm volatile("cp.async.commit_group;" ::: "memory")
#define CP_WAIT0()  asm volatile("cp.async.wait_group 0;" ::: "memory")
#define CP_WAIT1()  asm volatile("cp.async.wait_group 1;" ::: "memory")

__device__ __forceinline__ void ldsm4(uint32_t addr, uint32_t* r) {
    asm volatile("ldmatrix.sync.aligned.m8n8.x4.shared.b16 {%0,%1,%2,%3}, [%4];"
                 : "=r"(r[0]), "=r"(r[1]), "=r"(r[2]), "=r"(r[3]) : "r"(addr));
}
__device__ __forceinline__ void mma16816(float* c, const uint32_t* a, const uint32_t* b) {
    asm volatile(
        "mma.sync.aligned.m16n8k16.row.col.f32.f16.f16.f32 "
        "{%0,%1,%2,%3}, {%4,%5,%6,%7}, {%8,%9}, {%0,%1,%2,%3};"
        : "+f"(c[0]), "+f"(c[1]), "+f"(c[2]), "+f"(c[3])
        : "r"(a[0]), "r"(a[1]), "r"(a[2]), "r"(a[3]), "r"(b[0]), "r"(b[1]));
}

// ---------------- kNN (4 queries per thread, exact squared distances) ---------
__global__ __launch_bounds__(256) void knn_kernel(
    const float* __restrict__ xyz1, const float* __restrict__ xyz2)
{
    __shared__ float4 sp[S_];
    const int b = blockIdx.y;
    const int t = threadIdx.x;
    for (int s = t; s < S_; s += 256) {
        const float* p = xyz2 + ((size_t)b * S_ + s) * 3;
        sp[s] = make_float4(p[0], p[1], p[2], 0.0f);
    }
    __syncthreads();

    const int nb = blockIdx.x * 1024 + t;
    float qx[4], qy[4], qz[4];
    float d0[4], d1[4], d2[4];
    int   i0[4], i1[4], i2[4];
    #pragma unroll
    for (int j = 0; j < 4; j++) {
        const float* q = xyz1 + ((size_t)b * N_ + nb + j * 256) * 3;
        qx[j] = q[0]; qy[j] = q[1]; qz[j] = q[2];
        d0[j] = 3.4e38f; d1[j] = 3.4e38f; d2[j] = 3.4e38f;
        i0[j] = 0; i1[j] = 0; i2[j] = 0;
    }
    #pragma unroll 2
    for (int s = 0; s < S_; s++) {
        float4 p = sp[s];
        #pragma unroll
        for (int j = 0; j < 4; j++) {
            float dx = qx[j] - p.x, dy = qy[j] - p.y, dz = qz[j] - p.z;
            float d = fmaf(dz, dz, fmaf(dy, dy, dx * dx));
            if (d < d2[j]) {
                if (d < d1[j]) {
                    d2[j] = d1[j]; i2[j] = i1[j];
                    if (d < d0[j]) { d1[j] = d0[j]; i1[j] = i0[j]; d0[j] = d; i0[j] = s; }
                    else           { d1[j] = d;  i1[j] = s; }
                } else { d2[j] = d; i2[j] = s; }
            }
        }
    }
    #pragma unroll
    for (int j = 0; j < 4; j++) {
        float a = fmaxf(d0[j], 1e-10f), bb = fmaxf(d1[j], 1e-10f), c = fmaxf(d2[j], 1e-10f);
        float w0 = 1.0f / a, w1 = 1.0f / bb, w2 = 1.0f / c;
        float sw = w0 + w1 + w2;
        size_t base = ((size_t)b * N_ + nb + j * 256) * 3;
        g_idx[base] = i0[j]; g_idx[base + 1] = i1[j]; g_idx[base + 2] = i2[j];
        g_w[base] = w0 / sw; g_w[base + 1] = w1 / sw; g_w[base + 2] = w2 / sw;
    }
}

// ---------------- transpose points2 [B][C][S] -> [B][S][C] --------------------
__global__ void transpose_p2_kernel(const float* __restrict__ p2)
{
    __shared__ float tile[32][33];
    const int b  = blockIdx.z;
    const int s0 = blockIdx.x * 32;
    const int c0 = blockIdx.y * 32;
    #pragma unroll
    for (int r = 0; r < 4; r++) {
        int c = c0 + threadIdx.y + r * 8;
        tile[threadIdx.y + r * 8][threadIdx.x] =
            p2[((size_t)b * C2_ + c) * S_ + s0 + threadIdx.x];
    }
    __syncthreads();
    #pragma unroll
    for (int r = 0; r < 4; r++) {
        int s = s0 + threadIdx.y + r * 8;
        g_p2t[((size_t)b * S_ + s) * C2_ + c0 + threadIdx.x] =
            tile[threadIdx.x][threadIdx.y + r * 8];
    }
}

// ---------------- gather + weighted sum -> xcat channels [0,256) --------------
__global__ __launch_bounds__(256) void gather_kernel()
{
    const int b  = blockIdx.y;
    const int n0 = blockIdx.x * 32;
    const int t  = threadIdx.x;          // channel
    #pragma unroll 2
    for (int nl = 0; nl < 32; nl++) {
        size_t base = ((size_t)b * N_ + n0 + nl) * 3;
        int i0 = g_idx[base], i1 = g_idx[base + 1], i2 = g_idx[base + 2];
        float w0 = g_w[base], w1 = g_w[base + 1], w2 = g_w[base + 2];
        const float* r0 = g_p2t + ((size_t)b * S_ + i0) * C2_;
        const float* r1 = g_p2t + ((size_t)b * S_ + i1) * C2_;
        const float* r2 = g_p2t + ((size_t)b * S_ + i2) * C2_;
        float v = fmaf(w2, r2[t], fmaf(w1, r1[t], w0 * r0[t]));
        g_xq[((size_t)b * N_ + n0 + nl) * K1_ + t] = __float2half_rn(v);
    }
}

// ---------------- points1 transpose -> xcat channels [256,384) ----------------
__global__ void p1t_kernel(const float* __restrict__ p1)
{
    __shared__ float tile[32][33];
    const int b  = blockIdx.z;
    const int n0 = blockIdx.x * 32;
    const int c0 = blockIdx.y * 32;
    #pragma unroll
    for (int r = 0; r < 4; r++) {
        int c = c0 + threadIdx.y + r * 8;
        tile[threadIdx.y + r * 8][threadIdx.x] =
            p1[((size_t)b * C1_ + c) * N_ + n0 + threadIdx.x];
    }
    __syncthreads();
    #pragma unroll
    for (int r = 0; r < 4; r++) {
        int n = n0 + threadIdx.y + r * 8;
        float v = tile[threadIdx.x][threadIdx.y + r * 8];
        g_xq[((size_t)b * N_ + n) * K1_ + 256 + c0 + threadIdx.x] = __float2half_rn(v);
    }
}

// ---------------- weight fp16 convert -----------------------------------------
__global__ void wconv_kernel(const float* __restrict__ w,
                             __half* __restrict__ q, int n)
{
    int i = blockIdx.x * 256 + threadIdx.x;
    if (i < n) q[i] = __float2half_rn(w[i]);
}

// ---------------- mma.sync fp16 GEMM ------------------------------------------
// FUSE=0: D = W @ X             (layer 1; X = g_xq)
// FUSE=1: D = W @ relu(sc*X+bs) (layer 2; X = raw y1; affine in fp32 on B frags)
// CTA: 256 thr = 8 warps (4 in M x 2 in N). Warp tile 64x64.
// Epilogue: BN partials from fp32 accs; y stored fp16 via smem-staged flush.
template<int KDIM, bool FUSE>
__global__ __launch_bounds__(256) void gemm_mma(
    const __half* __restrict__ Aq, const __half* __restrict__ Bq,
    const float* __restrict__ bias, __half* __restrict__ Y,
    float* __restrict__ psum, float* __restrict__ pssq,
    const float* __restrict__ sbn)
{
    constexpr int NS = KDIM / 32;                 // K stages of 32
    constexpr uint32_t PITCH  = 80;               // 64B data + 16B pad
    constexpr uint32_t OFF_B  = 256u * PITCH;     // 20480
    constexpr uint32_t STAGE  = OFF_B + 128u * PITCH;  // 30720

    extern __shared__ char sdyn[];
    __shared__ float sm_s[2][256], sm_q[2][256];
    __shared__ float2 sscf[128], sbbf[128];       // fp32 per-channel-pair scale/bias

    const int tid  = threadIdx.x;
    const int lane = tid & 31, wid = tid >> 5;
    const int mw   = wid & 3;        // M block of 64
    const int nw   = wid >> 2;       // N block of 64
    const int b    = blockIdx.y;
    const int n0   = blockIdx.x * 128;
    const size_t bn0 = (size_t)b * N_ + n0;
    const uint32_t sb0 = smem_u32(sdyn);

    if (FUSE && tid < 128) {
        sscf[tid] = make_float2(sbn[2 * tid], sbn[2 * tid + 1]);
        sbbf[tid] = make_float2(sbn[256 + 2 * tid], sbn[256 + 2 * tid + 1]);
    }

    auto load_stage = [&](int kt, int buf) {
        uint32_t base = sb0 + (uint32_t)buf * STAGE;
        #pragma unroll
        for (int i = 0; i < 4; i++) {              // A: 256 rows x 4 chunks
            int c = tid + i * 256;
            int row = (c >> 2) & 255, ch = c & 3;
            const __half* src = Aq + (size_t)row * KDIM + kt + ch * 8;
            cpa16(base + (uint32_t)row * PITCH + ch * 16, src);
        }
        #pragma unroll
        for (int i = 0; i < 2; i++) {              // B: 128 rows x 4 chunks
            int c = tid + i * 256;
            int row = (c >> 2) & 127, ch = c & 3;
            const __half* src = Bq + (bn0 + row) * KDIM + kt + ch * 8;
            cpa16(base + OFF_B + (uint32_t)row * PITCH + ch * 16, src);
        }
        CP_COMMIT();
    };

    float acc[4][8][4] = {};

    load_stage(0, 0);

    #pragma unroll 1
    for (int s = 0; s < NS; s++) {
        if (s + 1 < NS) { load_stage((s + 1) * 32, (s + 1) & 1); CP_WAIT1(); }
        else            { CP_WAIT0(); }
        __syncthreads();

        uint32_t base = sb0 + (uint32_t)(s & 1) * STAGE;
        #pragma unroll
        for (int ks = 0; ks < 2; ks++) {
            uint32_t a[4][4];
            #pragma unroll
            for (int mt = 0; mt < 4; mt++) {
                uint32_t row = (uint32_t)(mw * 64 + mt * 16 + (lane & 15));
                ldsm4(base + row * PITCH + ks * 32 + ((lane >> 4) << 4), a[mt]);
            }
            // fp32 per-k scale/bias for this thread's B fragment positions
            float2 scA, scB, bsA, bsB;
            if (FUSE) {
                int kp = s * 16 + ks * 8 + (lane & 3);
                scA = sscf[kp];     bsA = sbbf[kp];
                scB = sscf[kp + 4]; bsB = sbbf[kp + 4];
            }
            #pragma unroll
            for (int ntp = 0; ntp < 4; ntp++) {
                uint32_t rowB = (uint32_t)(nw * 64 + ntp * 16
                               + ((lane >> 4) << 3) + (lane & 7));
                uint32_t bfr[4];
                ldsm4(base + OFF_B + rowB * PITCH
                      + ks * 32 + (((lane >> 3) & 1) << 4), bfr);
                if (FUSE) {
                    #pragma unroll
                    for (int j = 0; j < 4; j++) {
                        const float2 sc = (j & 1) ? scB : scA;
                        const float2 bs = (j & 1) ? bsB : bsA;
                        float2 v = __half22float2(*(__half2*)&bfr[j]);
                        v.x = fmaxf(fmaf(v.x, sc.x, bs.x), 0.0f);
                        v.y = fmaxf(fmaf(v.y, sc.y, bs.y), 0.0f);
                        *(__half2*)&bfr[j] = __floats2half2_rn(v.x, v.y);
                    }
                }
                #pragma unroll
                for (int h = 0; h < 2; h++) {
                    int nt = ntp * 2 + h;
                    #pragma unroll
                    for (int mt = 0; mt < 4; mt++)
                        mma16816(acc[mt][nt], a[mt], &bfr[h * 2]);
                }
            }
        }
        __syncthreads();
    }

    // ---- epilogue: bias, BN partials, smem-staged fp16 coalesced flush -------
    float* sy = (float*)sdyn;             // [64][260] per N-half
    const int r = lane >> 2;
    float csum[8] = {}, cssq[8] = {};

    #pragma unroll
    for (int half = 0; half < 2; half++) {
        if (nw == half) {
            #pragma unroll
            for (int mt = 0; mt < 4; mt++) {
                const int m0 = mw * 64 + mt * 16 + r;
                const int m1 = m0 + 8;
                const float bv0 = bias[m0], bv1 = bias[m1];
                #pragma unroll
                for (int nt = 0; nt < 8; nt++) {
                    float* c = acc[mt][nt];
                    int nl = nt * 8 + (lane & 3) * 2;
                    float v0 = c[0] + bv0, v1 = c[1] + bv0;
                    float v2 = c[2] + bv1, v3 = c[3] + bv1;
                    sy[nl * 260 + m0]       = v0;
                    sy[(nl + 1) * 260 + m0] = v1;
                    sy[nl * 260 + m1]       = v2;
                    sy[(nl + 1) * 260 + m1] = v3;
                    csum[mt * 2]     += v0 + v1;
                    cssq[mt * 2]     += fmaf(v0, v0, v1 * v1);
                    csum[mt * 2 + 1] += v2 + v3;
                    cssq[mt * 2 + 1] += fmaf(v2, v2, v3 * v3);
                }
            }
        }
        __syncthreads();
        // coalesced fp16 flush: 64 rows x 512B, two rows per iteration
        #pragma unroll 8
        for (int i = 0; i < 32; i++) {
            int row = i * 2 + (tid >> 7);
            int c2  = tid & 127;
            __half2 hp = __floats2half2_rn(sy[row * 260 + c2 * 2],
                                           sy[row * 260 + c2 * 2 + 1]);
            *(__half2*)(Y + (bn0 + half * 64 + row) * 256 + c2 * 2) = hp;
        }
        __syncthreads();
    }

    // BN partials
    #pragma unroll
    for (int j = 0; j < 8; j++) {
        csum[j] += __shfl_xor_sync(0xffffffffu, csum[j], 1);
        csum[j] += __shfl_xor_sync(0xffffffffu, csum[j], 2);
        cssq[j] += __shfl_xor_sync(0xffffffffu, cssq[j], 1);
        cssq[j] += __shfl_xor_sync(0xffffffffu, cssq[j], 2);
    }
    if ((lane & 3) == 0) {
        #pragma unroll
        for (int mt = 0; mt < 4; mt++) {
            #pragma unroll
            for (int h = 0; h < 2; h++) {
                int ch = mw * 64 + mt * 16 + r + h * 8;
                sm_s[nw][ch] = csum[mt * 2 + h];
                sm_q[nw][ch] = cssq[mt * 2 + h];
            }
        }
    }
    __syncthreads();
    {
        int cta = blockIdx.x + blockIdx.y * gridDim.x;
        psum[tid * 1024 + cta] = sm_s[0][tid] + sm_s[1][tid];
        pssq[tid * 1024 + cta] = sm_q[0][tid] + sm_q[1][tid];
    }
}

// ---------------- BN fold: reduce 1024 partials per channel -------------------
__global__ __launch_bounds__(256) void stats2_kernel(
    const float* __restrict__ g, const float* __restrict__ beta,
    float* __restrict__ sb)
{
    const int o = blockIdx.x;
    const int t = threadIdx.x;
    float s = 0.0f, ss = 0.0f;
    #pragma unroll
    for (int i = 0; i < 4; i++) {
        s  += g_psum[o * 1024 + t * 4 + i];
        ss += g_pssq[o * 1024 + t * 4 + i];
    }
    const int lane = t & 31, w = t >> 5;
    #pragma unroll
    for (int off = 16; off; off >>= 1) {
        s  += __shfl_down_sync(0xffffffffu, s,  off);
        ss += __shfl_down_sync(0xffffffffu, ss, off);
    }
    __shared__ float rs[8], rss[8];
    if (lane == 0) { rs[w] = s; rss[w] = ss; }
    __syncthreads();
    if (t == 0) {
        float ts = 0.0f, tss = 0.0f;
        #pragma unroll
        for (int i = 0; i < 8; i++) { ts += rs[i]; tss += rss[i]; }
        float mean = ts * CNT_INV;
        float var  = tss * CNT_INV - mean * mean;
        float rstd = rsqrtf(var + BN_EPS);
        float sc = g[o] * rstd;
        sb[o]       = sc;
        sb[256 + o] = beta[o] - mean * sc;
    }
}

// ---------------- final norm + relu + transpose -> out [B][256][N] ------------
__global__ __launch_bounds__(256) void outt_kernel(
    const __half* __restrict__ y, const float* __restrict__ sb,
    float* __restrict__ out)
{
    __shared__ float tile[32][33];
    const int b  = blockIdx.z;
    const int n0 = blockIdx.x * 32;
    const int m0 = blockIdx.y * 32;
    const float sc = sb[m0 + threadIdx.x];
    const float bs = sb[256 + m0 + threadIdx.x];
    #pragma unroll
    for (int r = 0; r < 4; r++) {
        int n = n0 + threadIdx.y + r * 8;
        float v = __half2float(y[((size_t)b * N_ + n) * 256 + m0 + threadIdx.x]);
        tile[threadIdx.y + r * 8][threadIdx.x] = fmaxf(fmaf(v, sc, bs), 0.0f);
    }
    __syncthreads();
    #pragma unroll
    for (int r = 0; r < 4; r++) {
        int m = m0 + threadIdx.y + r * 8;
        out[((size_t)b * 256 + m) * N_ + n0 + threadIdx.x] =
            tile[threadIdx.x][threadIdx.y + r * 8];
    }
}

// ---------------- launcher ----------------------------------------------------
extern "C" void kernel_launch(void* const* d_in, const int* in_sizes, int n_in,
                              void* d_out, int out_size)
{
    const float* xyz1 = (const float*)d_in[0];
    const float* xyz2 = (const float*)d_in[1];
    const float* pts1 = (const float*)d_in[2];
    const float* pts2 = (const float*)d_in[3];
    const float* W0   = (const float*)d_in[4];
    const float* b0   = (const float*)d_in[5];
    const float* gg0  = (const float*)d_in[6];
    const float* be0  = (const float*)d_in[7];
    const float* W1   = (const float*)d_in[8];
    const float* b1   = (const float*)d_in[9];
    const float* gg1  = (const float*)d_in[10];
    const float* be1  = (const float*)d_in[11];
    float* out = (float*)d_out;

    __half *xq, *w0q, *w1q, *y;
    float *psum, *pssq, *sb1, *sb2;
    cudaGetSymbolAddress((void**)&xq,  g_xq);
    cudaGetSymbolAddress((void**)&w0q, g_w0q);
    cudaGetSymbolAddress((void**)&w1q, g_w1q);
    cudaGetSymbolAddress((void**)&y,   g_y);
    cudaGetSymbolAddress((void**)&psum, g_psum);
    cudaGetSymbolAddress((void**)&pssq, g_pssq);
    cudaGetSymbolAddress((void**)&sb1, g_sb1);
    cudaGetSymbolAddress((void**)&sb2, g_sb2);

    const int GEMM_SMEM = 68096;   // max(2 stages 61440, sy 64*260*4=66560) +pad
    cudaFuncSetAttribute(gemm_mma<K1_, false>, cudaFuncAttributeMaxDynamicSharedMemorySize, GEMM_SMEM);
    cudaFuncSetAttribute(gemm_mma<O_,  true >, cudaFuncAttributeMaxDynamicSharedMemorySize, GEMM_SMEM);

    // prep
    wconv_kernel<<<(O_ * K1_ + 255) / 256, 256>>>(W0, w0q, O_ * K1_);
    wconv_kernel<<<(O_ * O_  + 255) / 256, 256>>>(W1, w1q, O_ * O_);
    knn_kernel<<<dim3(N_ / 1024, B_), 256>>>(xyz1, xyz2);
    transpose_p2_kernel<<<dim3(S_ / 32, C2_ / 32, B_), dim3(32, 8)>>>(pts2);
    gather_kernel<<<dim3(N_ / 32, B_), 256>>>();
    p1t_kernel<<<dim3(N_ / 32, C1_ / 32, B_), dim3(32, 8)>>>(pts1);

    // layer 1 -> y1
    gemm_mma<K1_, false><<<dim3(N_ / 128, B_), 256, GEMM_SMEM>>>(
        w0q, xq, b0, y, psum, pssq, nullptr);
    stats2_kernel<<<256, 256>>>(gg0, be0, sb1);

    // layer 2: reads raw y1, fp32 norm+relu on B fragments, writes y2 in place
    gemm_mma<O_, true><<<dim3(N_ / 128, B_), 256, GEMM_SMEM>>>(
        w1q, y, b1, y, psum, pssq, sb1);
    stats2_kernel<<<256, 256>>>(gg1, be1, sb2);

    // output
    outt_kernel<<<dim3(N_ / 32, 8, B_), dim3(32, 8)>>>(y, sb2, out);
}